// round 13
// baseline (speedup 1.0000x reference)
#include <cuda_runtime.h>
#include <cuda_bf16.h>
#include <math.h>

// ---------------- problem constants ----------------
#define BATCH 8
#define NN    512
#define DIN   64
#define HH    8
#define FF    128
#define LL    2
#define NEGV  (-9e15f)
#define LOG2E 1.4426950408889634f

// ---------------- scratch (device globals; no allocs) ----------------
__device__ float    g_h    [BATCH * NN * FF];
__device__ float    g_hh   [BATCH * HH * NN * FF];
__device__ float    g_multi[BATCH * NN * HH * FF];
__device__ float    g_h2   [BATCH * NN * FF];
__device__ float    g_part [8 * BATCH * NN * FF];     // split-K partials (S<=8)
__device__ unsigned g_adjp [BATCH * NN * 16];         // bit-packed adjacency
__device__ float    g_s1   [BATCH * HH * NN];
__device__ float    g_s2   [BATCH * HH * NN];
__device__ float    g_a1   [BATCH * HH * NN];         // (s1-mx)*log2e - log2(sum)
__device__ float    g_b1   [BATCH * HH * NN];         // (0.2 s1-mx)*log2e - log2(sum)
__device__ float    g_s2l  [BATCH * HH * NN];         // s2*log2e
__device__ float    g_t1   [BATCH * NN];
__device__ float    g_t2   [BATCH * NN];

// ---------------- reductions ----------------
__device__ __forceinline__ float warpSum(float v) {
#pragma unroll
    for (int o = 16; o > 0; o >>= 1) v += __shfl_xor_sync(0xffffffffu, v, o);
    return v;
}
__device__ __forceinline__ float warpMax(float v) {
#pragma unroll
    for (int o = 16; o > 0; o >>= 1) v = fmaxf(v, __shfl_xor_sync(0xffffffffu, v, o));
    return v;
}
__device__ __forceinline__ float blockSum128(float v) {
    __shared__ float sh[4];
    v = warpSum(v);
    __syncthreads();
    if ((threadIdx.x & 31) == 0) sh[threadIdx.x >> 5] = v;
    __syncthreads();
    return sh[0] + sh[1] + sh[2] + sh[3];
}
__device__ __forceinline__ float blockMax128(float v) {
    __shared__ float sh[4];
    v = warpMax(v);
    __syncthreads();
    if ((threadIdx.x & 31) == 0) sh[threadIdx.x >> 5] = v;
    __syncthreads();
    return fmaxf(fmaxf(sh[0], sh[1]), fmaxf(sh[2], sh[3]));
}

// ---------------- tf32 RNA rounding (bit trick == cvt.rna.tf32) ----------------
__device__ __forceinline__ unsigned rtf(float f) {
    return __float_as_uint(f) + 0x1000u;   // exact-0 stays 0 after 19-bit truncation
}
__device__ __forceinline__ void mma_tf32(float c[4], const unsigned a[4], const unsigned b0, const unsigned b1) {
    asm("mma.sync.aligned.m16n8k8.row.col.f32.tf32.tf32.f32 "
        "{%0,%1,%2,%3},{%4,%5,%6,%7},{%8,%9},{%0,%1,%2,%3};"
        : "+f"(c[0]), "+f"(c[1]), "+f"(c[2]), "+f"(c[3])
        : "r"(a[0]), "r"(a[1]), "r"(a[2]), "r"(a[3]), "r"(b0), "r"(b1));
}
__device__ __forceinline__ float ex2f(float x) {
    float r;
    asm("ex2.approx.f32 %0, %1;" : "=f"(r) : "f"(x));
    return r;
}
// att element in log2 domain: bit ? ex2(max(A1+s2l, fma(0.2,s2l,B1))) : 0
__device__ __forceinline__ unsigned att_val(unsigned bit, float s2l, float A1, float B1) {
    const float arg = fmaxf(A1 + s2l, fmaf(0.2f, s2l, B1));
    const float r = bit ? ex2f(arg) : 0.f;
    return rtf(r);
}

// ---------------- adjacency bit-pack (one-time) ----------------
__global__ void k_pack(const int* __restrict__ adj, unsigned* __restrict__ packed) {
    const long long row = blockIdx.x;       // b*NN + n
    const int t = threadIdx.x;              // 0..127
    const int w = t >> 5, lane = t & 31;
#pragma unroll
    for (int p = 0; p < 4; p++) {
        const int col = p * 128 + w * 32 + lane;
        const unsigned m = __ballot_sync(0xffffffffu, adj[row * NN + col] > 0);
        if (lane == 0) packed[row * 16 + p * 4 + w] = m;
    }
}

// ---------------- input projection ----------------
__global__ void k_proj(const float* __restrict__ x, const float* __restrict__ Wp,
                       const float* __restrict__ bp, float* __restrict__ h) {
    __shared__ float xs[DIN];
    const int row = blockIdx.x;
    const int t = threadIdx.x;
    if (t < DIN) xs[t] = x[(long)row * DIN + t];
    __syncthreads();
    float acc = bp[t];
#pragma unroll
    for (int i = 0; i < DIN; i++) acc = fmaf(xs[i], Wp[i * FF + t], acc);
    h[(long)row * FF + t] = fmaxf(acc, 0.f);
}

// ---------------- pipelined TF32 tensor-core GEMM ----------------
// C[M,128] = A[M,KC*S] @ B[KC*S,128], row-major, ldb = 128.
// Block tile 128x128, K-step 16, double-buffered smem, 8 warps 4(M)x2(N).
// EPI: 0 none, 1 ELU, 2 plain + fused svec. ATT: 1 = A computed from log2 att factors.
#define GBM 128
#define GBK 16
#define ALD 24
#define BLD 136
template <int KC, int S, int EPI, int ATT>
__global__ __launch_bounds__(256, 2)
void k_gemm_t(const float* __restrict__ A, const float* __restrict__ B,
              float* __restrict__ C, float* __restrict__ Cpart,
              int M,
              long long sAb, long long sAh,
              long long sBb, long long sBh,
              long long sCb, long long sCh,
              int Hb, int ldc, long long TOT,
              const unsigned* __restrict__ adjp,
              const float* __restrict__ a1p, const float* __restrict__ b1p,
              const float* __restrict__ s2lp,
              const float* __restrict__ avec,
              float* __restrict__ o1, float* __restrict__ o2) {
    const int zz = blockIdx.z;
    const int s = zz % S;
    const int z2 = zz / S;
    const int bz = z2 / Hb, hz = z2 % Hb;
    A += bz * sAb + hz * sAh + (long long)s * KC;
    B += bz * sBb + hz * sBh + (long long)s * KC * 128;
    C += bz * sCb + hz * sCh;
    const int bm = blockIdx.y * GBM;
    constexpr long long Kfull = (long long)KC * S;
    const int soff = s * KC;

    __shared__ unsigned As[2][GBM][ALD];   // [m][perm_k]
    __shared__ unsigned Bs[2][GBK][BLD];   // [k][perm_n]
    __shared__ float ash[2 * FF];          // EPI==2
    __shared__ float sv1[GBM], sv2[GBM];   // EPI==2

    const int tid  = threadIdx.x;
    const int lane = tid & 31;
    const int wid  = tid >> 5;
    const int wm = (wid & 3) * 32;
    const int wn = (wid >> 2) * 64;
    const int q = lane & 3;
    const int g = lane >> 2;

    const int arow0 = tid >> 2;
    const int ac = tid & 3;
    const int aw0 = (ac & 1) + 8 * (ac >> 1);
    const int br = tid >> 5;
    const int bc = lane * 4;

    if (EPI == 2 && tid < 2 * FF) ash[tid] = (avec + (long long)hz * 2 * FF)[tid];

    // ATT row-constant factors for this thread's 2 staging rows
    float A1r[2], B1r[2];
    const unsigned* adjP = adjp;
    const float* s2A = s2lp;
    if (ATT) {
        adjP = adjp + (long long)bz * NN * 16;
        s2A = s2lp + (long long)z2 * NN;
#pragma unroll
        for (int p = 0; p < 2; p++) {
            const long long ridx = (long long)z2 * NN + bm + arow0 + p * 64;
            A1r[p] = a1p[ridx];
            B1r[p] = b1p[ridx];
        }
    }

    float acc[2][8][4];
#pragma unroll
    for (int i = 0; i < 2; i++)
#pragma unroll
        for (int j = 0; j < 8; j++)
#pragma unroll
            for (int r = 0; r < 4; r++) acc[i][j][r] = 0.f;

    // ---- prologue: stage tile 0 ----
    if (ATT) {
        const int mg = soff + ac * 4;
        const float4 sv = *(const float4*)(s2A + mg);
        const int wix = mg >> 5, bo = mg & 31;
#pragma unroll
        for (int p = 0; p < 2; p++) {
            const int row = arow0 + p * 64;
            const unsigned w = adjP[(long long)(bm + row) * 16 + wix];
            As[0][row][aw0 + 0] = att_val((w >> (bo + 0)) & 1u, sv.x, A1r[p], B1r[p]);
            As[0][row][aw0 + 2] = att_val((w >> (bo + 1)) & 1u, sv.y, A1r[p], B1r[p]);
            As[0][row][aw0 + 4] = att_val((w >> (bo + 2)) & 1u, sv.z, A1r[p], B1r[p]);
            As[0][row][aw0 + 6] = att_val((w >> (bo + 3)) & 1u, sv.w, A1r[p], B1r[p]);
        }
    } else {
#pragma unroll
        for (int p = 0; p < 2; p++) {
            const int row = arow0 + p * 64;
            const float4 av = *(const float4*)(A + (long long)(bm + row) * Kfull + ac * 4);
            As[0][row][aw0 + 0] = rtf(av.x);
            As[0][row][aw0 + 2] = rtf(av.y);
            As[0][row][aw0 + 4] = rtf(av.z);
            As[0][row][aw0 + 6] = rtf(av.w);
        }
    }
#pragma unroll
    for (int p = 0; p < 2; p++) {
        const int rr = br + p * 8;
        const float4 bv = *(const float4*)(B + (long long)rr * 128 + bc);
#pragma unroll
        for (int j = 0; j < 4; j++) {
            const int n = bc + j;
            const int sn = ((n >> 3) & 7) + ((n & 7) << 3) + (n & 64);
            Bs[0][rr][sn] = rtf(j == 0 ? bv.x : j == 1 ? bv.y : j == 2 ? bv.z : bv.w);
        }
    }
    __syncthreads();

    int buf = 0;
#pragma unroll 2
    for (int k0 = 0; k0 < KC; k0 += GBK) {
        const bool pre = (k0 + GBK) < KC;
        float4 pa[2], pb[2];
        unsigned paw[2];
        float4 psv;
        if (pre) {
            const int kn = k0 + GBK;
            if (ATT) {
                const int mg = soff + kn + ac * 4;
                psv = *(const float4*)(s2A + mg);
                const int wix = mg >> 5;
#pragma unroll
                for (int p = 0; p < 2; p++)
                    paw[p] = adjP[(long long)(bm + arow0 + p * 64) * 16 + wix];
            } else {
#pragma unroll
                for (int p = 0; p < 2; p++) {
                    const int row = arow0 + p * 64;
                    pa[p] = *(const float4*)(A + (long long)(bm + row) * Kfull + kn + ac * 4);
                }
            }
#pragma unroll
            for (int p = 0; p < 2; p++) {
                const int rr = br + p * 8;
                pb[p] = *(const float4*)(B + (long long)(kn + rr) * 128 + bc);
            }
        }

        // ---- compute on current buffer ----
#pragma unroll
        for (int ks = 0; ks < GBK; ks += 8) {
            const unsigned* r0 = &Bs[buf][ks + q][0];
            const unsigned* r1 = &Bs[buf][ks + q + 4][0];
            const uint4 b0a = *(const uint4*)(r0 + wn + 8 * g);
            const uint4 b0b = *(const uint4*)(r0 + wn + 8 * g + 4);
            const uint4 b1a = *(const uint4*)(r1 + wn + 8 * g);
            const uint4 b1b = *(const uint4*)(r1 + wn + 8 * g + 4);
            const unsigned bu0[8] = {b0a.x, b0a.y, b0a.z, b0a.w, b0b.x, b0b.y, b0b.z, b0b.w};
            const unsigned bu1[8] = {b1a.x, b1a.y, b1a.z, b1a.w, b1b.x, b1b.y, b1b.z, b1b.w};
            unsigned af[2][4];
#pragma unroll
            for (int mt = 0; mt < 2; mt++) {
                const int m0 = wm + mt * 16 + g;
                const uint2 a0 = *(const uint2*)&As[buf][m0][ks + 2 * q];
                const uint2 a1 = *(const uint2*)&As[buf][m0 + 8][ks + 2 * q];
                af[mt][0] = a0.x; af[mt][1] = a1.x; af[mt][2] = a0.y; af[mt][3] = a1.y;
            }
#pragma unroll
            for (int mt = 0; mt < 2; mt++)
#pragma unroll
                for (int nt = 0; nt < 8; nt++)
                    mma_tf32(acc[mt][nt], af[mt], bu0[nt], bu1[nt]);
        }

        // ---- stage next tile ----
        if (pre) {
            const int nb = buf ^ 1;
            if (ATT) {
                const int bo = (soff + k0 + GBK + ac * 4) & 31;
#pragma unroll
                for (int p = 0; p < 2; p++) {
                    const int row = arow0 + p * 64;
                    As[nb][row][aw0 + 0] = att_val((paw[p] >> (bo + 0)) & 1u, psv.x, A1r[p], B1r[p]);
                    As[nb][row][aw0 + 2] = att_val((paw[p] >> (bo + 1)) & 1u, psv.y, A1r[p], B1r[p]);
                    As[nb][row][aw0 + 4] = att_val((paw[p] >> (bo + 2)) & 1u, psv.z, A1r[p], B1r[p]);
                    As[nb][row][aw0 + 6] = att_val((paw[p] >> (bo + 3)) & 1u, psv.w, A1r[p], B1r[p]);
                }
            } else {
#pragma unroll
                for (int p = 0; p < 2; p++) {
                    const int row = arow0 + p * 64;
                    As[nb][row][aw0 + 0] = rtf(pa[p].x);
                    As[nb][row][aw0 + 2] = rtf(pa[p].y);
                    As[nb][row][aw0 + 4] = rtf(pa[p].z);
                    As[nb][row][aw0 + 6] = rtf(pa[p].w);
                }
            }
#pragma unroll
            for (int p = 0; p < 2; p++) {
                const int rr = br + p * 8;
#pragma unroll
                for (int j = 0; j < 4; j++) {
                    const int n = bc + j;
                    const int sn = ((n >> 3) & 7) + ((n & 7) << 3) + (n & 64);
                    Bs[nb][rr][sn] = rtf(j == 0 ? pb[p].x : j == 1 ? pb[p].y : j == 2 ? pb[p].z : pb[p].w);
                }
            }
            __syncthreads();
            buf = nb;
        }
    }

    // ---- epilogue ----
    float p1[2][2], p2[2][2];
    if (EPI == 2) {
#pragma unroll
        for (int mt = 0; mt < 2; mt++)
#pragma unroll
            for (int hf = 0; hf < 2; hf++) { p1[mt][hf] = 0.f; p2[mt][hf] = 0.f; }
    }
#pragma unroll
    for (int mt = 0; mt < 2; mt++) {
#pragma unroll
        for (int half = 0; half < 2; half++) {
            const int row = wm + mt * 16 + g + half * 8;
            if (S == 1) {
                float* crow = C + (long long)(bm + row) * ldc;
#pragma unroll
                for (int nt = 0; nt < 8; nt++) {
                    const int col = wn + nt * 8 + 2 * q;
                    float v0 = acc[mt][nt][half * 2 + 0];
                    float v1 = acc[mt][nt][half * 2 + 1];
                    if (EPI == 1) {
                        v0 = v0 > 0.f ? v0 : (__expf(v0) - 1.f);
                        v1 = v1 > 0.f ? v1 : (__expf(v1) - 1.f);
                    }
                    if (EPI == 2) {
                        p1[mt][half] += v0 * ash[col] + v1 * ash[col + 1];
                        p2[mt][half] += v0 * ash[FF + col] + v1 * ash[FF + col + 1];
                    }
                    *(float2*)(crow + col) = make_float2(v0, v1);
                }
            } else {
                float* prow = Cpart + (long long)s * TOT + ((long long)z2 * M + bm + row) * 128;
#pragma unroll
                for (int nt = 0; nt < 8; nt++) {
                    const int col = wn + nt * 8 + 2 * q;
                    *(float2*)(prow + col) = make_float2(acc[mt][nt][half * 2 + 0],
                                                         acc[mt][nt][half * 2 + 1]);
                }
            }
        }
    }

    if (EPI == 2) {
#pragma unroll
        for (int mt = 0; mt < 2; mt++)
#pragma unroll
            for (int hf = 0; hf < 2; hf++) {
                p1[mt][hf] += __shfl_xor_sync(0xffffffffu, p1[mt][hf], 1);
                p1[mt][hf] += __shfl_xor_sync(0xffffffffu, p1[mt][hf], 2);
                p2[mt][hf] += __shfl_xor_sync(0xffffffffu, p2[mt][hf], 1);
                p2[mt][hf] += __shfl_xor_sync(0xffffffffu, p2[mt][hf], 2);
            }
        __syncthreads();
        if ((wid >> 2) == 0 && q == 0) {
#pragma unroll
            for (int mt = 0; mt < 2; mt++)
#pragma unroll
                for (int hf = 0; hf < 2; hf++) {
                    const int r = wm + mt * 16 + hf * 8 + g;
                    sv1[r] = p1[mt][hf];
                    sv2[r] = p2[mt][hf];
                }
        }
        __syncthreads();
        if ((wid >> 2) == 1 && q == 0) {
#pragma unroll
            for (int mt = 0; mt < 2; mt++)
#pragma unroll
                for (int hf = 0; hf < 2; hf++) {
                    const int r = wm + mt * 16 + hf * 8 + g;
                    const long long oidx = (long long)z2 * NN + bm + r;
                    o1[oidx] = sv1[r] + p1[mt][hf];
                    o2[oidx] = sv2[r] + p2[mt][hf];
                }
        }
    }
}

// ---------------- row stats (packed adj): log2-domain attention factors ----------------
__global__ void k_stats(const unsigned* __restrict__ adjp, const float* __restrict__ s1,
                        const float* __restrict__ s2, float* __restrict__ a1,
                        float* __restrict__ b1, float* __restrict__ s2l, int Hb) {
    const int n = blockIdx.x, h = blockIdx.y, b = blockIdx.z;
    const int t = threadIdx.x;
    const int m0 = t * 4;
    const long idx = ((long)b * Hb + h) * NN + n;
    const float* s2row = s2 + ((long)b * Hb + h) * NN;
    const float s1v = s1[idx];

    // packed adj word: 4 bits for this thread live in word t>>3 at offset (m0&31)
    const unsigned w = adjp[((long)b * NN + n) * 16 + (t >> 3)];
    const int bo = m0 & 31;
    const float4 sv = *(const float4*)(s2row + m0);

    float v[4];
    {
        float e0 = s1v + sv.x; e0 = e0 > 0.f ? e0 : 0.2f * e0; v[0] = ((w >> (bo + 0)) & 1u) ? e0 : NEGV;
        float e1 = s1v + sv.y; e1 = e1 > 0.f ? e1 : 0.2f * e1; v[1] = ((w >> (bo + 1)) & 1u) ? e1 : NEGV;
        float e2 = s1v + sv.z; e2 = e2 > 0.f ? e2 : 0.2f * e2; v[2] = ((w >> (bo + 2)) & 1u) ? e2 : NEGV;
        float e3 = s1v + sv.w; e3 = e3 > 0.f ? e3 : 0.2f * e3; v[3] = ((w >> (bo + 3)) & 1u) ? e3 : NEGV;
    }
    float mv = fmaxf(fmaxf(v[0], v[1]), fmaxf(v[2], v[3]));
    mv = blockMax128(mv);
    float sum = 0.f;
#pragma unroll
    for (int j = 0; j < 4; j++) sum += __expf(v[j] - mv);
    sum = blockSum128(sum);
    if (t == 0) {
        const float li = -__log2f(sum);
        a1[idx] = (s1v - mv) * LOG2E + li;
        b1[idx] = (0.2f * s1v - mv) * LOG2E + li;
        s2l[idx] = s2[idx] * LOG2E;
    }
}

// ---------------- fused split-K(8) reduce + svec ----------------
__global__ void k_red_svec(const float* __restrict__ part, float* __restrict__ h2,
                           const float* __restrict__ a, float* __restrict__ t1,
                           float* __restrict__ t2, long long TOT) {
    const int row = blockIdx.x;
    const int t = threadIdx.x;
    const long long i = (long long)row * FF + t;
    float v = 0.f;
#pragma unroll
    for (int j = 0; j < 8; j++) v += part[(long long)j * TOT + i];
    h2[i] = v;
    float p1 = v * a[t];
    float p2 = v * a[FF + t];
    p1 = blockSum128(p1);
    p2 = blockSum128(p2);
    if (t == 0) {
        t1[row] = p1;
        t2[row] = p2;
    }
}

// ---------------- fused split-K(8) reduce + residual + layernorm (+relu) ----------------
__global__ void k_red_lnorm(const float* __restrict__ part, const float* __restrict__ res,
                            const float* __restrict__ g, const float* __restrict__ bb,
                            float* __restrict__ dst, int do_relu, long long TOT) {
    const int row = blockIdx.x;
    const int t = threadIdx.x;
    const long long i = (long long)row * FF + t;
    float o = 0.f;
#pragma unroll
    for (int j = 0; j < 8; j++) o += part[(long long)j * TOT + i];
    const float y = o + res[i];
    const float mu = blockSum128(y) * (1.f / FF);
    const float d = y - mu;
    const float var = blockSum128(d * d) * (1.f / FF);
    float r = d * rsqrtf(var + 1e-5f) * g[t] + bb[t];
    if (do_relu) r = fmaxf(r, 0.f);
    dst[i] = r;
}

// ---------------- host orchestration ----------------
extern "C" void kernel_launch(void* const* d_in, const int* in_sizes, int n_in,
                              void* d_out, int out_size) {
    (void)in_sizes; (void)n_in; (void)out_size;
    const float* x       = (const float*)d_in[0];
    const int*   adj     = (const int*)  d_in[1];
    const float* Wp      = (const float*)d_in[2];
    const float* bp      = (const float*)d_in[3];
    const float* W_heads = (const float*)d_in[4];
    const float* a_heads = (const float*)d_in[5];
    const float* W_out   = (const float*)d_in[6];
    const float* a_out   = (const float*)d_in[7];
    const float* ln_g    = (const float*)d_in[8];
    const float* ln_b    = (const float*)d_in[9];
    float* out = (float*)d_out;

    float *p_h, *p_hh, *p_multi, *p_h2, *p_part;
    float *p_s1, *p_s2, *p_a1, *p_b1, *p_s2l, *p_t1, *p_t2;
    unsigned* p_adjp;
    cudaGetSymbolAddress((void**)&p_h, g_h);
    cudaGetSymbolAddress((void**)&p_hh, g_hh);
    cudaGetSymbolAddress((void**)&p_multi, g_multi);
    cudaGetSymbolAddress((void**)&p_h2, g_h2);
    cudaGetSymbolAddress((void**)&p_part, g_part);
    cudaGetSymbolAddress((void**)&p_adjp, g_adjp);
    cudaGetSymbolAddress((void**)&p_s1, g_s1);
    cudaGetSymbolAddress((void**)&p_s2, g_s2);
    cudaGetSymbolAddress((void**)&p_a1, g_a1);
    cudaGetSymbolAddress((void**)&p_b1, g_b1);
    cudaGetSymbolAddress((void**)&p_s2l, g_s2l);
    cudaGetSymbolAddress((void**)&p_t1, g_t1);
    cudaGetSymbolAddress((void**)&p_t2, g_t2);

    const long long TOT = (long long)BATCH * NN * FF;   // 524288

    k_pack<<<BATCH * NN, 128>>>(adj, p_adjp);
    k_proj<<<BATCH * NN, 128>>>(x, Wp, bp, p_h);

    for (int l = 0; l < LL; l++) {
        // 1) per-head projection + fused svec
        k_gemm_t<128, 1, 2, 0><<<dim3(1, NN / GBM, BATCH * HH), 256>>>(
            p_h, W_heads + (long)l * HH * FF * FF, p_hh, p_part,
            NN,
            (long long)NN * FF, 0,
            0, (long long)FF * FF,
            (long long)HH * NN * FF, (long long)NN * FF,
            HH, FF, 0,
            nullptr, nullptr, nullptr, nullptr,
            a_heads + (long)l * HH * 2 * FF, p_s1, p_s2);

        // 2) softmax factors (log2 domain, packed adj)
        k_stats<<<dim3(NN, HH, BATCH), 128>>>(p_adjp, p_s1, p_s2, p_a1, p_b1, p_s2l, HH);

        // 3) fused (softmax ∘ att) @ hh, ELU, scatter into multi
        k_gemm_t<512, 1, 1, 1><<<dim3(1, NN / GBM, BATCH * HH), 256>>>(
            nullptr, p_hh, p_multi, p_part,
            NN,
            0, 0,
            (long long)HH * NN * FF, (long long)NN * FF,
            (long long)NN * HH * FF, (long long)FF,
            HH, HH * FF, 0,
            p_adjp, p_a1, p_b1, p_s2l,
            nullptr, nullptr, nullptr);

        // 4) out projection split-K S=8 + fused reduce+svec
        k_gemm_t<128, 8, 0, 0><<<dim3(1, (BATCH * NN) / GBM, 8), 256>>>(
            p_multi, W_out + (long)l * HH * FF * FF, p_h2, p_part,
            BATCH * NN,
            0, 0, 0, 0, 0, 0,
            1, FF, TOT,
            nullptr, nullptr, nullptr, nullptr,
            nullptr, nullptr, nullptr);
        k_red_svec<<<BATCH * NN, 128>>>(p_part, p_h2, a_out + (long)l * 2 * FF,
                                        p_t1, p_t2, TOT);

        // 5) single-head softmax factors
        k_stats<<<dim3(NN, 1, BATCH), 128>>>(p_adjp, p_t1, p_t2, p_a1, p_b1, p_s2l, 1);

        // 6) fused (softmax ∘ att2) @ h2 split-K S=8 + fused reduce+residual+layernorm
        k_gemm_t<64, 8, 0, 1><<<dim3(1, NN / GBM, BATCH * 8), 256>>>(
            nullptr, p_h2, nullptr, p_part,
            NN,
            0, 0,
            (long long)NN * FF, 0,
            0, 0,
            1, FF, TOT,
            p_adjp, p_a1, p_b1, p_s2l,
            nullptr, nullptr, nullptr);
        float* dst = (l == LL - 1) ? out : p_h;
        k_red_lnorm<<<BATCH * NN, 128>>>(p_part, p_h,
                                         ln_g + (long)l * FF, ln_b + (long)l * FF,
                                         dst, (l < LL - 1) ? 1 : 0, TOT);
    }
}

// round 14
// speedup vs baseline: 1.2904x; 1.2904x over previous
#include <cuda_runtime.h>
#include <cuda_bf16.h>
#include <math.h>

// ---------------- problem constants ----------------
#define BATCH 8
#define NN    512
#define DIN   64
#define HH    8
#define FF    128
#define LL    2
#define NEGV  (-9e15f)
#define LOG2E 1.4426950408889634f

// ---------------- scratch (device globals; no allocs) ----------------
__device__ float    g_h    [BATCH * NN * FF];
__device__ float    g_hh   [BATCH * HH * NN * FF];
__device__ float    g_multi[BATCH * NN * HH * FF];
__device__ float    g_h2   [BATCH * NN * FF];
__device__ float    g_part [8 * BATCH * NN * FF];     // split-K partials (S<=8)
__device__ unsigned g_adjp [BATCH * NN * 16];         // bit-packed adjacency
__device__ float    g_s1   [BATCH * HH * NN];
__device__ float    g_s2   [BATCH * HH * NN];
__device__ float    g_a1   [BATCH * HH * NN];
__device__ float    g_b1   [BATCH * HH * NN];
__device__ float    g_s2l  [BATCH * HH * NN];
__device__ float    g_t1   [BATCH * NN];
__device__ float    g_t2   [BATCH * NN];

// ---------------- reductions ----------------
__device__ __forceinline__ float warpSum(float v) {
#pragma unroll
    for (int o = 16; o > 0; o >>= 1) v += __shfl_xor_sync(0xffffffffu, v, o);
    return v;
}
__device__ __forceinline__ float warpMax(float v) {
#pragma unroll
    for (int o = 16; o > 0; o >>= 1) v = fmaxf(v, __shfl_xor_sync(0xffffffffu, v, o));
    return v;
}
__device__ __forceinline__ float blockSum128(float v) {
    __shared__ float sh[4];
    v = warpSum(v);
    __syncthreads();
    if ((threadIdx.x & 31) == 0) sh[threadIdx.x >> 5] = v;
    __syncthreads();
    return sh[0] + sh[1] + sh[2] + sh[3];
}
__device__ __forceinline__ float blockMax128(float v) {
    __shared__ float sh[4];
    v = warpMax(v);
    __syncthreads();
    if ((threadIdx.x & 31) == 0) sh[threadIdx.x >> 5] = v;
    __syncthreads();
    return fmaxf(fmaxf(sh[0], sh[1]), fmaxf(sh[2], sh[3]));
}

// ---------------- numeric helpers ----------------
__device__ __forceinline__ unsigned rtf(float f) {
    return __float_as_uint(f) + 0x1000u;   // RNA-to-tf32 via int add
}
__device__ __forceinline__ void mma_tf32(float c[4], const unsigned a[4], const unsigned b0, const unsigned b1) {
    asm("mma.sync.aligned.m16n8k8.row.col.f32.tf32.tf32.f32 "
        "{%0,%1,%2,%3},{%4,%5,%6,%7},{%8,%9},{%0,%1,%2,%3};"
        : "+f"(c[0]), "+f"(c[1]), "+f"(c[2]), "+f"(c[3])
        : "r"(a[0]), "r"(a[1]), "r"(a[2]), "r"(a[3]), "r"(b0), "r"(b1));
}
__device__ __forceinline__ void mma_bf16(float c[4], const unsigned a[4], const unsigned b0, const unsigned b1) {
    asm("mma.sync.aligned.m16n8k16.row.col.f32.bf16.bf16.f32 "
        "{%0,%1,%2,%3},{%4,%5,%6,%7},{%8,%9},{%0,%1,%2,%3};"
        : "+f"(c[0]), "+f"(c[1]), "+f"(c[2]), "+f"(c[3])
        : "r"(a[0]), "r"(a[1]), "r"(a[2]), "r"(a[3]), "r"(b0), "r"(b1));
}
// pack (lo,hi) floats -> bf16x2 (lo in bits [15:0])
__device__ __forceinline__ unsigned bf2(float lo, float hi) {
    unsigned r;
    asm("cvt.rn.bf16x2.f32 %0, %1, %2;" : "=r"(r) : "f"(hi), "f"(lo));
    return r;
}
__device__ __forceinline__ float ex2f(float x) {
    float r;
    asm("ex2.approx.f32 %0, %1;" : "=f"(r) : "f"(x));
    return r;
}
__device__ __forceinline__ float att_f(unsigned bit, float s2l, float A1, float B1) {
    const float arg = fmaxf(A1 + s2l, fmaf(0.2f, s2l, B1));
    return bit ? ex2f(arg) : 0.f;
}
__device__ __forceinline__ unsigned att_val(unsigned bit, float s2l, float A1, float B1) {
    return rtf(att_f(bit, s2l, A1, B1));
}

// ---------------- adjacency bit-pack (one-time) ----------------
__global__ void k_pack(const int* __restrict__ adj, unsigned* __restrict__ packed) {
    const long long row = blockIdx.x;
    const int t = threadIdx.x;
    const int w = t >> 5, lane = t & 31;
#pragma unroll
    for (int p = 0; p < 4; p++) {
        const int col = p * 128 + w * 32 + lane;
        const unsigned m = __ballot_sync(0xffffffffu, adj[row * NN + col] > 0);
        if (lane == 0) packed[row * 16 + p * 4 + w] = m;
    }
}

// ---------------- input projection ----------------
__global__ void k_proj(const float* __restrict__ x, const float* __restrict__ Wp,
                       const float* __restrict__ bp, float* __restrict__ h) {
    __shared__ float xs[DIN];
    const int row = blockIdx.x;
    const int t = threadIdx.x;
    if (t < DIN) xs[t] = x[(long)row * DIN + t];
    __syncthreads();
    float acc = bp[t];
#pragma unroll
    for (int i = 0; i < DIN; i++) acc = fmaf(xs[i], Wp[i * FF + t], acc);
    h[(long)row * FF + t] = fmaxf(acc, 0.f);
}

// ================= tf32 GEMM (projections) =================
#define GBM 128
#define GBK 16
#define ALD 24
#define BLD 136
template <int KC, int S, int EPI>
__global__ __launch_bounds__(256, 2)
void k_gemm_t(const float* __restrict__ A, const float* __restrict__ B,
              float* __restrict__ C, float* __restrict__ Cpart,
              int M,
              long long sAb, long long sAh,
              long long sBb, long long sBh,
              long long sCb, long long sCh,
              int Hb, int ldc, long long TOT,
              const float* __restrict__ avec,
              float* __restrict__ o1, float* __restrict__ o2) {
    const int zz = blockIdx.z;
    const int s = zz % S;
    const int z2 = zz / S;
    const int bz = z2 / Hb, hz = z2 % Hb;
    A += bz * sAb + hz * sAh + (long long)s * KC;
    B += bz * sBb + hz * sBh + (long long)s * KC * 128;
    C += bz * sCb + hz * sCh;
    const int bm = blockIdx.y * GBM;
    constexpr long long Kfull = (long long)KC * S;

    __shared__ unsigned As[2][GBM][ALD];
    __shared__ unsigned Bs[2][GBK][BLD];
    __shared__ float ash[2 * FF];
    __shared__ float sv1[GBM], sv2[GBM];

    const int tid  = threadIdx.x;
    const int lane = tid & 31;
    const int wid  = tid >> 5;
    const int wm = (wid & 3) * 32;
    const int wn = (wid >> 2) * 64;
    const int q = lane & 3;
    const int g = lane >> 2;

    const int arow0 = tid >> 2;
    const int ac = tid & 3;
    const int aw0 = (ac & 1) + 8 * (ac >> 1);
    const int br = tid >> 5;
    const int bc = lane * 4;

    if (EPI == 2 && tid < 2 * FF) ash[tid] = (avec + (long long)hz * 2 * FF)[tid];

    float acc[2][8][4];
#pragma unroll
    for (int i = 0; i < 2; i++)
#pragma unroll
        for (int j = 0; j < 8; j++)
#pragma unroll
            for (int r = 0; r < 4; r++) acc[i][j][r] = 0.f;

#pragma unroll
    for (int p = 0; p < 2; p++) {
        const int row = arow0 + p * 64;
        const float4 av = *(const float4*)(A + (long long)(bm + row) * Kfull + ac * 4);
        As[0][row][aw0 + 0] = rtf(av.x);
        As[0][row][aw0 + 2] = rtf(av.y);
        As[0][row][aw0 + 4] = rtf(av.z);
        As[0][row][aw0 + 6] = rtf(av.w);
    }
#pragma unroll
    for (int p = 0; p < 2; p++) {
        const int rr = br + p * 8;
        const float4 bv = *(const float4*)(B + (long long)rr * 128 + bc);
#pragma unroll
        for (int j = 0; j < 4; j++) {
            const int n = bc + j;
            const int sn = ((n >> 3) & 7) + ((n & 7) << 3) + (n & 64);
            Bs[0][rr][sn] = rtf(j == 0 ? bv.x : j == 1 ? bv.y : j == 2 ? bv.z : bv.w);
        }
    }
    __syncthreads();

    int buf = 0;
#pragma unroll 2
    for (int k0 = 0; k0 < KC; k0 += GBK) {
        const bool pre = (k0 + GBK) < KC;
        float4 pa[2], pb[2];
        if (pre) {
            const int kn = k0 + GBK;
#pragma unroll
            for (int p = 0; p < 2; p++) {
                const int row = arow0 + p * 64;
                pa[p] = *(const float4*)(A + (long long)(bm + row) * Kfull + kn + ac * 4);
            }
#pragma unroll
            for (int p = 0; p < 2; p++) {
                const int rr = br + p * 8;
                pb[p] = *(const float4*)(B + (long long)(kn + rr) * 128 + bc);
            }
        }
#pragma unroll
        for (int ks = 0; ks < GBK; ks += 8) {
            const unsigned* r0 = &Bs[buf][ks + q][0];
            const unsigned* r1 = &Bs[buf][ks + q + 4][0];
            const uint4 b0a = *(const uint4*)(r0 + wn + 8 * g);
            const uint4 b0b = *(const uint4*)(r0 + wn + 8 * g + 4);
            const uint4 b1a = *(const uint4*)(r1 + wn + 8 * g);
            const uint4 b1b = *(const uint4*)(r1 + wn + 8 * g + 4);
            const unsigned bu0[8] = {b0a.x, b0a.y, b0a.z, b0a.w, b0b.x, b0b.y, b0b.z, b0b.w};
            const unsigned bu1[8] = {b1a.x, b1a.y, b1a.z, b1a.w, b1b.x, b1b.y, b1b.z, b1b.w};
            unsigned af[2][4];
#pragma unroll
            for (int mt = 0; mt < 2; mt++) {
                const int m0 = wm + mt * 16 + g;
                const uint2 a0 = *(const uint2*)&As[buf][m0][ks + 2 * q];
                const uint2 a1 = *(const uint2*)&As[buf][m0 + 8][ks + 2 * q];
                af[mt][0] = a0.x; af[mt][1] = a1.x; af[mt][2] = a0.y; af[mt][3] = a1.y;
            }
#pragma unroll
            for (int mt = 0; mt < 2; mt++)
#pragma unroll
                for (int nt = 0; nt < 8; nt++)
                    mma_tf32(acc[mt][nt], af[mt], bu0[nt], bu1[nt]);
        }
        if (pre) {
            const int nb = buf ^ 1;
#pragma unroll
            for (int p = 0; p < 2; p++) {
                const int row = arow0 + p * 64;
                As[nb][row][aw0 + 0] = rtf(pa[p].x);
                As[nb][row][aw0 + 2] = rtf(pa[p].y);
                As[nb][row][aw0 + 4] = rtf(pa[p].z);
                As[nb][row][aw0 + 6] = rtf(pa[p].w);
            }
#pragma unroll
            for (int p = 0; p < 2; p++) {
                const int rr = br + p * 8;
#pragma unroll
                for (int j = 0; j < 4; j++) {
                    const int n = bc + j;
                    const int sn = ((n >> 3) & 7) + ((n & 7) << 3) + (n & 64);
                    Bs[nb][rr][sn] = rtf(j == 0 ? pb[p].x : j == 1 ? pb[p].y : j == 2 ? pb[p].z : pb[p].w);
                }
            }
            __syncthreads();
            buf = nb;
        }
    }

    float p1[2][2], p2[2][2];
    if (EPI == 2) {
#pragma unroll
        for (int mt = 0; mt < 2; mt++)
#pragma unroll
            for (int hf = 0; hf < 2; hf++) { p1[mt][hf] = 0.f; p2[mt][hf] = 0.f; }
    }
#pragma unroll
    for (int mt = 0; mt < 2; mt++) {
#pragma unroll
        for (int half = 0; half < 2; half++) {
            const int row = wm + mt * 16 + g + half * 8;
            if (S == 1) {
                float* crow = C + (long long)(bm + row) * ldc;
#pragma unroll
                for (int nt = 0; nt < 8; nt++) {
                    const int col = wn + nt * 8 + 2 * q;
                    float v0 = acc[mt][nt][half * 2 + 0];
                    float v1 = acc[mt][nt][half * 2 + 1];
                    if (EPI == 1) {
                        v0 = v0 > 0.f ? v0 : (__expf(v0) - 1.f);
                        v1 = v1 > 0.f ? v1 : (__expf(v1) - 1.f);
                    }
                    if (EPI == 2) {
                        p1[mt][half] += v0 * ash[col] + v1 * ash[col + 1];
                        p2[mt][half] += v0 * ash[FF + col] + v1 * ash[FF + col + 1];
                    }
                    *(float2*)(crow + col) = make_float2(v0, v1);
                }
            } else {
                float* prow = Cpart + (long long)s * TOT + ((long long)z2 * M + bm + row) * 128;
#pragma unroll
                for (int nt = 0; nt < 8; nt++) {
                    const int col = wn + nt * 8 + 2 * q;
                    *(float2*)(prow + col) = make_float2(acc[mt][nt][half * 2 + 0],
                                                         acc[mt][nt][half * 2 + 1]);
                }
            }
        }
    }

    if (EPI == 2) {
#pragma unroll
        for (int mt = 0; mt < 2; mt++)
#pragma unroll
            for (int hf = 0; hf < 2; hf++) {
                p1[mt][hf] += __shfl_xor_sync(0xffffffffu, p1[mt][hf], 1);
                p1[mt][hf] += __shfl_xor_sync(0xffffffffu, p1[mt][hf], 2);
                p2[mt][hf] += __shfl_xor_sync(0xffffffffu, p2[mt][hf], 1);
                p2[mt][hf] += __shfl_xor_sync(0xffffffffu, p2[mt][hf], 2);
            }
        __syncthreads();
        if ((wid >> 2) == 0 && q == 0) {
#pragma unroll
            for (int mt = 0; mt < 2; mt++)
#pragma unroll
                for (int hf = 0; hf < 2; hf++) {
                    const int r = wm + mt * 16 + hf * 8 + g;
                    sv1[r] = p1[mt][hf];
                    sv2[r] = p2[mt][hf];
                }
        }
        __syncthreads();
        if ((wid >> 2) == 1 && q == 0) {
#pragma unroll
            for (int mt = 0; mt < 2; mt++)
#pragma unroll
                for (int hf = 0; hf < 2; hf++) {
                    const int r = wm + mt * 16 + hf * 8 + g;
                    const long long oidx = (long long)z2 * NN + bm + r;
                    o1[oidx] = sv1[r] + p1[mt][hf];
                    o2[oidx] = sv2[r] + p2[mt][hf];
                }
        }
    }
}

// ================= bf16 fused attention GEMM =================
// C[M,128] = att[M, KC*S] @ B[KC*S,128]; att generated on the fly (log2 factors).
// Tile 128x128, K-step 16 via m16n8k16 bf16. Operands stored row-major as bf16x2
// words, pitch 8, word index perm p(k2)=((k2&3)<<1)|(k2>>2), XOR swizzle on bits[2:1].
#define SWX(row, w) ((w) ^ ((((row) >> 2) & 3) << 1))
template <int KC, int S, int EPI>
__global__ __launch_bounds__(256, 2)
void k_gatt16(const float* __restrict__ B,
              float* __restrict__ C, float* __restrict__ Cpart,
              int M,
              long long sBb, long long sBh,
              long long sCb, long long sCh,
              int Hb, int ldc, long long TOT,
              const unsigned* __restrict__ adjp,
              const float* __restrict__ a1p, const float* __restrict__ b1p,
              const float* __restrict__ s2lp) {
    const int zz = blockIdx.z;
    const int s = zz % S;
    const int z2 = zz / S;
    const int bz = z2 / Hb, hz = z2 % Hb;
    B += bz * sBb + hz * sBh + (long long)s * KC * 128;
    C += bz * sCb + hz * sCh;
    const int bm = blockIdx.y * 128;
    const int soff = s * KC;

    __shared__ unsigned As[2][128][8];   // att bf16x2
    __shared__ unsigned Bs[2][128][8];   // B^T bf16x2 ([n][k2-perm])

    const int tid  = threadIdx.x;
    const int lane = tid & 31;
    const int wid  = tid >> 5;
    const int wm = (wid & 3) * 32;
    const int wn = (wid >> 2) * 64;
    const int q = lane & 3;
    const int g = lane >> 2;

    // A staging: thread handles k = {2j,2j+1,2j+8,2j+9}, rows arow0, arow0+64
    const int aj = tid & 3;
    const int arow0 = tid >> 2;
    // B staging: thread handles col n=bn, k2 sets {h,h+4} and {h+2,h+6}
    const int bn = tid & 127;
    const int bh = tid >> 7;

    const unsigned* adjP = adjp + (long long)bz * NN * 16;
    const float* s2A = s2lp + (long long)z2 * NN;
    float A1r[2], B1r[2];
#pragma unroll
    for (int p = 0; p < 2; p++) {
        const long long ridx = (long long)z2 * NN + bm + arow0 + p * 64;
        A1r[p] = a1p[ridx];
        B1r[p] = b1p[ridx];
    }

    float acc[2][8][4];
#pragma unroll
    for (int i = 0; i < 2; i++)
#pragma unroll
        for (int j = 0; j < 8; j++)
#pragma unroll
            for (int r = 0; r < 4; r++) acc[i][j][r] = 0.f;

    // ---- staging helpers (inline) ----
    // A tile for chunk base kk0 (global col offset), into buffer bb
#define STAGE_A(bb, kk0, w0a, w1a, f2a, f2b)                                      \
    {                                                                              \
        const int bo = ((kk0) & 31) + 2 * aj;                                      \
        _Pragma("unroll")                                                          \
        for (int p = 0; p < 2; p++) {                                              \
            const int row = arow0 + p * 64;                                        \
            const unsigned w = (p == 0) ? (w0a) : (w1a);                           \
            const float f0 = att_f((w >> (bo + 0)) & 1u, (f2a).x, A1r[p], B1r[p]); \
            const float f1 = att_f((w >> (bo + 1)) & 1u, (f2a).y, A1r[p], B1r[p]); \
            const float f2 = att_f((w >> (bo + 8)) & 1u, (f2b).x, A1r[p], B1r[p]); \
            const float f3 = att_f((w >> (bo + 9)) & 1u, (f2b).y, A1r[p], B1r[p]); \
            *(uint2*)&As[bb][row][SWX(row, 2 * aj)] =                              \
                make_uint2(bf2(f0, f1), bf2(f2, f3));                              \
        }                                                                          \
    }
#define STAGE_B(bb, fv)                                                            \
    {                                                                              \
        *(uint2*)&Bs[bb][bn][SWX(bn, 2 * bh)] =                                    \
            make_uint2(bf2((fv)[0], (fv)[1]), bf2((fv)[2], (fv)[3]));              \
        *(uint2*)&Bs[bb][bn][SWX(bn, 2 * bh + 4)] =                                \
            make_uint2(bf2((fv)[4], (fv)[5]), bf2((fv)[6], (fv)[7]));              \
    }

    // B gmem rows for chunk k0: {2h,2h+1,2h+8,2h+9,2h+4,2h+5,2h+12,2h+13}
    const int brow[8] = {2 * bh, 2 * bh + 1, 2 * bh + 8, 2 * bh + 9,
                         2 * bh + 4, 2 * bh + 5, 2 * bh + 12, 2 * bh + 13};

    // ---- prologue: chunk 0 ----
    {
        const int kk0 = soff;
        const int wix = kk0 >> 5;
        const unsigned w0 = adjP[(long long)(bm + arow0) * 16 + wix];
        const unsigned w1 = adjP[(long long)(bm + arow0 + 64) * 16 + wix];
        const float2 f2a = *(const float2*)(s2A + kk0 + 2 * aj);
        const float2 f2b = *(const float2*)(s2A + kk0 + 2 * aj + 8);
        STAGE_A(0, kk0, w0, w1, f2a, f2b);
        float fv[8];
#pragma unroll
        for (int i = 0; i < 8; i++) fv[i] = B[(long long)brow[i] * 128 + bn];
        STAGE_B(0, fv);
    }
    __syncthreads();

    int buf = 0;
#pragma unroll 2
    for (int k0 = 0; k0 < KC; k0 += 16) {
        const bool pre = (k0 + 16) < KC;
        unsigned pw0, pw1;
        float2 pf2a, pf2b;
        float pfv[8];
        if (pre) {
            const int kk0 = soff + k0 + 16;
            const int wix = kk0 >> 5;
            pw0 = adjP[(long long)(bm + arow0) * 16 + wix];
            pw1 = adjP[(long long)(bm + arow0 + 64) * 16 + wix];
            pf2a = *(const float2*)(s2A + kk0 + 2 * aj);
            pf2b = *(const float2*)(s2A + kk0 + 2 * aj + 8);
#pragma unroll
            for (int i = 0; i < 8; i++)
                pfv[i] = B[(long long)(k0 + 16 + brow[i]) * 128 + bn];
        }

        // ---- compute: one m16n8k16 per (mt,nt) ----
        {
            unsigned bu[8][2];
#pragma unroll
            for (int nt = 0; nt < 8; nt++) {
                const int n0 = wn + nt * 8 + g;
                const uint2 t = *(const uint2*)&Bs[buf][n0][SWX(n0, 2 * q)];
                bu[nt][0] = t.x;
                bu[nt][1] = t.y;
            }
            unsigned af[2][4];
#pragma unroll
            for (int mt = 0; mt < 2; mt++) {
                const int m0 = wm + mt * 16 + g;
                const uint2 a = *(const uint2*)&As[buf][m0][SWX(m0, 2 * q)];
                const uint2 b = *(const uint2*)&As[buf][m0 + 8][SWX(m0 + 8, 2 * q)];
                af[mt][0] = a.x; af[mt][1] = b.x; af[mt][2] = a.y; af[mt][3] = b.y;
            }
#pragma unroll
            for (int mt = 0; mt < 2; mt++)
#pragma unroll
                for (int nt = 0; nt < 8; nt++)
                    mma_bf16(acc[mt][nt], af[mt], bu[nt][0], bu[nt][1]);
        }

        if (pre) {
            const int nb = buf ^ 1;
            STAGE_A(nb, soff + k0 + 16, pw0, pw1, pf2a, pf2b);
            STAGE_B(nb, pfv);
            __syncthreads();
            buf = nb;
        }
    }

    // ---- epilogue ----
#pragma unroll
    for (int mt = 0; mt < 2; mt++) {
#pragma unroll
        for (int half = 0; half < 2; half++) {
            const int row = wm + mt * 16 + g + half * 8;
            if (S == 1) {
                float* crow = C + (long long)(bm + row) * ldc;
#pragma unroll
                for (int nt = 0; nt < 8; nt++) {
                    const int col = wn + nt * 8 + 2 * q;
                    float v0 = acc[mt][nt][half * 2 + 0];
                    float v1 = acc[mt][nt][half * 2 + 1];
                    if (EPI == 1) {
                        v0 = v0 > 0.f ? v0 : (__expf(v0) - 1.f);
                        v1 = v1 > 0.f ? v1 : (__expf(v1) - 1.f);
                    }
                    *(float2*)(crow + col) = make_float2(v0, v1);
                }
            } else {
                float* prow = Cpart + (long long)s * TOT + ((long long)z2 * M + bm + row) * 128;
#pragma unroll
                for (int nt = 0; nt < 8; nt++) {
                    const int col = wn + nt * 8 + 2 * q;
                    *(float2*)(prow + col) = make_float2(acc[mt][nt][half * 2 + 0],
                                                         acc[mt][nt][half * 2 + 1]);
                }
            }
        }
    }
#undef STAGE_A
#undef STAGE_B
}

// ---------------- row stats (packed adj): log2-domain attention factors ----------------
__global__ void k_stats(const unsigned* __restrict__ adjp, const float* __restrict__ s1,
                        const float* __restrict__ s2, float* __restrict__ a1,
                        float* __restrict__ b1, float* __restrict__ s2l, int Hb) {
    const int n = blockIdx.x, h = blockIdx.y, b = blockIdx.z;
    const int t = threadIdx.x;
    const int m0 = t * 4;
    const long idx = ((long)b * Hb + h) * NN + n;
    const float* s2row = s2 + ((long)b * Hb + h) * NN;
    const float s1v = s1[idx];

    const unsigned w = adjp[((long)b * NN + n) * 16 + (t >> 3)];
    const int bo = m0 & 31;
    const float4 sv = *(const float4*)(s2row + m0);

    float v[4];
    {
        float e0 = s1v + sv.x; e0 = e0 > 0.f ? e0 : 0.2f * e0; v[0] = ((w >> (bo + 0)) & 1u) ? e0 : NEGV;
        float e1 = s1v + sv.y; e1 = e1 > 0.f ? e1 : 0.2f * e1; v[1] = ((w >> (bo + 1)) & 1u) ? e1 : NEGV;
        float e2 = s1v + sv.z; e2 = e2 > 0.f ? e2 : 0.2f * e2; v[2] = ((w >> (bo + 2)) & 1u) ? e2 : NEGV;
        float e3 = s1v + sv.w; e3 = e3 > 0.f ? e3 : 0.2f * e3; v[3] = ((w >> (bo + 3)) & 1u) ? e3 : NEGV;
    }
    float mv = fmaxf(fmaxf(v[0], v[1]), fmaxf(v[2], v[3]));
    mv = blockMax128(mv);
    float sum = 0.f;
#pragma unroll
    for (int j = 0; j < 4; j++) sum += __expf(v[j] - mv);
    sum = blockSum128(sum);
    if (t == 0) {
        const float li = -__log2f(sum);
        a1[idx] = (s1v - mv) * LOG2E + li;
        b1[idx] = (0.2f * s1v - mv) * LOG2E + li;
        s2l[idx] = s2[idx] * LOG2E;
    }
}

// ---------------- fused split-K(8) reduce + svec ----------------
__global__ void k_red_svec(const float* __restrict__ part, float* __restrict__ h2,
                           const float* __restrict__ a, float* __restrict__ t1,
                           float* __restrict__ t2, long long TOT) {
    const int row = blockIdx.x;
    const int t = threadIdx.x;
    const long long i = (long long)row * FF + t;
    float v = 0.f;
#pragma unroll
    for (int j = 0; j < 8; j++) v += part[(long long)j * TOT + i];
    h2[i] = v;
    float p1 = v * a[t];
    float p2 = v * a[FF + t];
    p1 = blockSum128(p1);
    p2 = blockSum128(p2);
    if (t == 0) {
        t1[row] = p1;
        t2[row] = p2;
    }
}

// ---------------- fused split-K(8) reduce + residual + layernorm (+relu) ----------------
__global__ void k_red_lnorm(const float* __restrict__ part, const float* __restrict__ res,
                            const float* __restrict__ g, const float* __restrict__ bb,
                            float* __restrict__ dst, int do_relu, long long TOT) {
    const int row = blockIdx.x;
    const int t = threadIdx.x;
    const long long i = (long long)row * FF + t;
    float o = 0.f;
#pragma unroll
    for (int j = 0; j < 8; j++) o += part[(long long)j * TOT + i];
    const float y = o + res[i];
    const float mu = blockSum128(y) * (1.f / FF);
    const float d = y - mu;
    const float var = blockSum128(d * d) * (1.f / FF);
    float r = d * rsqrtf(var + 1e-5f) * g[t] + bb[t];
    if (do_relu) r = fmaxf(r, 0.f);
    dst[i] = r;
}

// ---------------- host orchestration ----------------
extern "C" void kernel_launch(void* const* d_in, const int* in_sizes, int n_in,
                              void* d_out, int out_size) {
    (void)in_sizes; (void)n_in; (void)out_size;
    const float* x       = (const float*)d_in[0];
    const int*   adj     = (const int*)  d_in[1];
    const float* Wp      = (const float*)d_in[2];
    const float* bp      = (const float*)d_in[3];
    const float* W_heads = (const float*)d_in[4];
    const float* a_heads = (const float*)d_in[5];
    const float* W_out   = (const float*)d_in[6];
    const float* a_out   = (const float*)d_in[7];
    const float* ln_g    = (const float*)d_in[8];
    const float* ln_b    = (const float*)d_in[9];
    float* out = (float*)d_out;

    float *p_h, *p_hh, *p_multi, *p_h2, *p_part;
    float *p_s1, *p_s2, *p_a1, *p_b1, *p_s2l, *p_t1, *p_t2;
    unsigned* p_adjp;
    cudaGetSymbolAddress((void**)&p_h, g_h);
    cudaGetSymbolAddress((void**)&p_hh, g_hh);
    cudaGetSymbolAddress((void**)&p_multi, g_multi);
    cudaGetSymbolAddress((void**)&p_h2, g_h2);
    cudaGetSymbolAddress((void**)&p_part, g_part);
    cudaGetSymbolAddress((void**)&p_adjp, g_adjp);
    cudaGetSymbolAddress((void**)&p_s1, g_s1);
    cudaGetSymbolAddress((void**)&p_s2, g_s2);
    cudaGetSymbolAddress((void**)&p_a1, g_a1);
    cudaGetSymbolAddress((void**)&p_b1, g_b1);
    cudaGetSymbolAddress((void**)&p_s2l, g_s2l);
    cudaGetSymbolAddress((void**)&p_t1, g_t1);
    cudaGetSymbolAddress((void**)&p_t2, g_t2);

    const long long TOT = (long long)BATCH * NN * FF;   // 524288

    k_pack<<<BATCH * NN, 128>>>(adj, p_adjp);
    k_proj<<<BATCH * NN, 128>>>(x, Wp, bp, p_h);

    for (int l = 0; l < LL; l++) {
        // 1) per-head projection + fused svec (tf32)
        k_gemm_t<128, 1, 2><<<dim3(1, NN / GBM, BATCH * HH), 256>>>(
            p_h, W_heads + (long)l * HH * FF * FF, p_hh, p_part,
            NN,
            (long long)NN * FF, 0,
            0, (long long)FF * FF,
            (long long)HH * NN * FF, (long long)NN * FF,
            HH, FF, 0,
            a_heads + (long)l * HH * 2 * FF, p_s1, p_s2);

        // 2) softmax factors (log2 domain, packed adj)
        k_stats<<<dim3(NN, HH, BATCH), 128>>>(p_adjp, p_s1, p_s2, p_a1, p_b1, p_s2l, HH);

        // 3) fused (softmax ∘ att) @ hh in bf16, ELU, scatter into multi
        k_gatt16<512, 1, 1><<<dim3(1, NN / 128, BATCH * HH), 256>>>(
            p_hh, p_multi, p_part,
            NN,
            (long long)HH * NN * FF, (long long)NN * FF,
            (long long)NN * HH * FF, (long long)FF,
            HH, HH * FF, 0,
            p_adjp, p_a1, p_b1, p_s2l);

        // 4) out projection split-K S=8 (tf32) + fused reduce+svec
        k_gemm_t<128, 8, 0><<<dim3(1, (BATCH * NN) / GBM, 8), 256>>>(
            p_multi, W_out + (long)l * HH * FF * FF, p_h2, p_part,
            BATCH * NN,
            0, 0, 0, 0, 0, 0,
            1, FF, TOT,
            nullptr, nullptr, nullptr);
        k_red_svec<<<BATCH * NN, 128>>>(p_part, p_h2, a_out + (long)l * 2 * FF,
                                        p_t1, p_t2, TOT);

        // 5) single-head softmax factors
        k_stats<<<dim3(NN, 1, BATCH), 128>>>(p_adjp, p_t1, p_t2, p_a1, p_b1, p_s2l, 1);

        // 6) fused (softmax ∘ att2) @ h2 in bf16, split-K S=8 + fused reduce+ln
        k_gatt16<64, 8, 0><<<dim3(1, NN / 128, BATCH * 8), 256>>>(
            p_h2, nullptr, p_part,
            NN,
            (long long)NN * FF, 0,
            0, 0,
            1, FF, TOT,
            p_adjp, p_a1, p_b1, p_s2l);
        float* dst = (l == LL - 1) ? out : p_h;
        k_red_lnorm<<<BATCH * NN, 128>>>(p_part, p_h,
                                         ln_g + (long)l * FF, ln_b + (long)l * FF,
                                         dst, (l < LL - 1) ? 1 : 0, TOT);
    }
}

// round 16
// speedup vs baseline: 1.3788x; 1.0685x over previous
#include <cuda_runtime.h>
#include <cuda_bf16.h>
#include <math.h>

// ---------------- problem constants ----------------
#define BATCH 8
#define NN    512
#define DIN   64
#define HH    8
#define FF    128
#define LL    2
#define NEGV  (-9e15f)
#define LOG2E 1.4426950408889634f

// ---------------- scratch (device globals; no allocs) ----------------
__device__ float    g_h    [BATCH * NN * FF];
__device__ float    g_hh   [BATCH * HH * NN * FF];
__device__ float    g_multi[BATCH * NN * HH * FF];
__device__ float    g_h2   [BATCH * NN * FF];
__device__ float    g_part [8 * BATCH * NN * FF];
__device__ unsigned g_adjp [BATCH * NN * 16];
__device__ float    g_s1   [BATCH * HH * NN];
__device__ float    g_s2   [BATCH * HH * NN];
__device__ float    g_a1   [BATCH * HH * NN];
__device__ float    g_b1   [BATCH * HH * NN];
__device__ float    g_s2l  [BATCH * HH * NN];
__device__ float    g_t1   [BATCH * NN];
__device__ float    g_t2   [BATCH * NN];

// ---------------- reductions ----------------
__device__ __forceinline__ float warpSum(float v) {
#pragma unroll
    for (int o = 16; o > 0; o >>= 1) v += __shfl_xor_sync(0xffffffffu, v, o);
    return v;
}
__device__ __forceinline__ float warpMax(float v) {
#pragma unroll
    for (int o = 16; o > 0; o >>= 1) v = fmaxf(v, __shfl_xor_sync(0xffffffffu, v, o));
    return v;
}
__device__ __forceinline__ float blockSum128(float v) {
    __shared__ float sh[4];
    v = warpSum(v);
    __syncthreads();
    if ((threadIdx.x & 31) == 0) sh[threadIdx.x >> 5] = v;
    __syncthreads();
    return sh[0] + sh[1] + sh[2] + sh[3];
}

// ---------------- numeric helpers ----------------
__device__ __forceinline__ unsigned rtf(float f) {
    return __float_as_uint(f) + 0x1000u;   // RNA-to-tf32 via int add
}
__device__ __forceinline__ void mma_tf32(float c[4], const unsigned a[4], const unsigned b0, const unsigned b1) {
    asm("mma.sync.aligned.m16n8k8.row.col.f32.tf32.tf32.f32 "
        "{%0,%1,%2,%3},{%4,%5,%6,%7},{%8,%9},{%0,%1,%2,%3};"
        : "+f"(c[0]), "+f"(c[1]), "+f"(c[2]), "+f"(c[3])
        : "r"(a[0]), "r"(a[1]), "r"(a[2]), "r"(a[3]), "r"(b0), "r"(b1));
}
__device__ __forceinline__ void mma_bf16(float c[4], const unsigned a[4], const unsigned b0, const unsigned b1) {
    asm("mma.sync.aligned.m16n8k16.row.col.f32.bf16.bf16.f32 "
        "{%0,%1,%2,%3},{%4,%5,%6,%7},{%8,%9},{%0,%1,%2,%3};"
        : "+f"(c[0]), "+f"(c[1]), "+f"(c[2]), "+f"(c[3])
        : "r"(a[0]), "r"(a[1]), "r"(a[2]), "r"(a[3]), "r"(b0), "r"(b1));
}
__device__ __forceinline__ unsigned bf2(float lo, float hi) {
    unsigned r;
    asm("cvt.rn.bf16x2.f32 %0, %1, %2;" : "=r"(r) : "f"(hi), "f"(lo));
    return r;
}
__device__ __forceinline__ float ex2f(float x) {
    float r;
    asm("ex2.approx.f32 %0, %1;" : "=f"(r) : "f"(x));
    return r;
}
__device__ __forceinline__ float att_f(unsigned bit, float s2l, float A1, float B1) {
    const float arg = fmaxf(A1 + s2l, fmaf(0.2f, s2l, B1));
    return bit ? ex2f(arg) : 0.f;
}

// ---------------- adjacency bit-pack (one-time) ----------------
__global__ void k_pack(const int* __restrict__ adj, unsigned* __restrict__ packed) {
    const long long row = blockIdx.x;
    const int t = threadIdx.x;
    const int w = t >> 5, lane = t & 31;
#pragma unroll
    for (int p = 0; p < 4; p++) {
        const int col = p * 128 + w * 32 + lane;
        const unsigned m = __ballot_sync(0xffffffffu, adj[row * NN + col] > 0);
        if (lane == 0) packed[row * 16 + p * 4 + w] = m;
    }
}

// ---------------- input projection ----------------
__global__ void k_proj(const float* __restrict__ x, const float* __restrict__ Wp,
                       const float* __restrict__ bp, float* __restrict__ h) {
    __shared__ float xs[DIN];
    const int row = blockIdx.x;
    const int t = threadIdx.x;
    if (t < DIN) xs[t] = x[(long)row * DIN + t];
    __syncthreads();
    float acc = bp[t];
#pragma unroll
    for (int i = 0; i < DIN; i++) acc = fmaf(xs[i], Wp[i * FF + t], acc);
    h[(long)row * FF + t] = fmaxf(acc, 0.f);
}

// ================= tf32 GEMM (projections — logit path stays tf32) =================
#define GBM 128
#define GBK 16
#define ALD 24
#define BLD 136
template <int KC, int S, int EPI>
__global__ __launch_bounds__(256, 2)
void k_gemm_t(const float* __restrict__ A, const float* __restrict__ B,
              float* __restrict__ C, float* __restrict__ Cpart,
              int M,
              long long sAb, long long sAh,
              long long sBb, long long sBh,
              long long sCb, long long sCh,
              int Hb, int ldc, long long TOT,
              const float* __restrict__ avec,
              float* __restrict__ o1, float* __restrict__ o2) {
    const int zz = blockIdx.z;
    const int s = zz % S;
    const int z2 = zz / S;
    const int bz = z2 / Hb, hz = z2 % Hb;
    A += bz * sAb + hz * sAh + (long long)s * KC;
    B += bz * sBb + hz * sBh + (long long)s * KC * 128;
    C += bz * sCb + hz * sCh;
    const int bm = blockIdx.y * GBM;
    constexpr long long Kfull = (long long)KC * S;

    __shared__ unsigned As[2][GBM][ALD];
    __shared__ unsigned Bs[2][GBK][BLD];
    __shared__ float ash[2 * FF];
    __shared__ float sv1[GBM], sv2[GBM];

    const int tid  = threadIdx.x;
    const int lane = tid & 31;
    const int wid  = tid >> 5;
    const int wm = (wid & 3) * 32;
    const int wn = (wid >> 2) * 64;
    const int q = lane & 3;
    const int g = lane >> 2;

    const int arow0 = tid >> 2;
    const int ac = tid & 3;
    const int aw0 = (ac & 1) + 8 * (ac >> 1);
    const int br = tid >> 5;
    const int bc = lane * 4;

    if (EPI == 2 && tid < 2 * FF) ash[tid] = (avec + (long long)hz * 2 * FF)[tid];

    float acc[2][8][4];
#pragma unroll
    for (int i = 0; i < 2; i++)
#pragma unroll
        for (int j = 0; j < 8; j++)
#pragma unroll
            for (int r = 0; r < 4; r++) acc[i][j][r] = 0.f;

#pragma unroll
    for (int p = 0; p < 2; p++) {
        const int row = arow0 + p * 64;
        const float4 av = *(const float4*)(A + (long long)(bm + row) * Kfull + ac * 4);
        As[0][row][aw0 + 0] = rtf(av.x);
        As[0][row][aw0 + 2] = rtf(av.y);
        As[0][row][aw0 + 4] = rtf(av.z);
        As[0][row][aw0 + 6] = rtf(av.w);
    }
#pragma unroll
    for (int p = 0; p < 2; p++) {
        const int rr = br + p * 8;
        const float4 bv = *(const float4*)(B + (long long)rr * 128 + bc);
#pragma unroll
        for (int j = 0; j < 4; j++) {
            const int n = bc + j;
            const int sn = ((n >> 3) & 7) + ((n & 7) << 3) + (n & 64);
            Bs[0][rr][sn] = rtf(j == 0 ? bv.x : j == 1 ? bv.y : j == 2 ? bv.z : bv.w);
        }
    }
    __syncthreads();

    int buf = 0;
#pragma unroll 2
    for (int k0 = 0; k0 < KC; k0 += GBK) {
        const bool pre = (k0 + GBK) < KC;
        float4 pa[2], pb[2];
        if (pre) {
            const int kn = k0 + GBK;
#pragma unroll
            for (int p = 0; p < 2; p++) {
                const int row = arow0 + p * 64;
                pa[p] = *(const float4*)(A + (long long)(bm + row) * Kfull + kn + ac * 4);
            }
#pragma unroll
            for (int p = 0; p < 2; p++) {
                const int rr = br + p * 8;
                pb[p] = *(const float4*)(B + (long long)(kn + rr) * 128 + bc);
            }
        }
#pragma unroll
        for (int ks = 0; ks < GBK; ks += 8) {
            const unsigned* r0 = &Bs[buf][ks + q][0];
            const unsigned* r1 = &Bs[buf][ks + q + 4][0];
            const uint4 b0a = *(const uint4*)(r0 + wn + 8 * g);
            const uint4 b0b = *(const uint4*)(r0 + wn + 8 * g + 4);
            const uint4 b1a = *(const uint4*)(r1 + wn + 8 * g);
            const uint4 b1b = *(const uint4*)(r1 + wn + 8 * g + 4);
            const unsigned bu0[8] = {b0a.x, b0a.y, b0a.z, b0a.w, b0b.x, b0b.y, b0b.z, b0b.w};
            const unsigned bu1[8] = {b1a.x, b1a.y, b1a.z, b1a.w, b1b.x, b1b.y, b1b.z, b1b.w};
            unsigned af[2][4];
#pragma unroll
            for (int mt = 0; mt < 2; mt++) {
                const int m0 = wm + mt * 16 + g;
                const uint2 a0 = *(const uint2*)&As[buf][m0][ks + 2 * q];
                const uint2 a1 = *(const uint2*)&As[buf][m0 + 8][ks + 2 * q];
                af[mt][0] = a0.x; af[mt][1] = a1.x; af[mt][2] = a0.y; af[mt][3] = a1.y;
            }
#pragma unroll
            for (int mt = 0; mt < 2; mt++)
#pragma unroll
                for (int nt = 0; nt < 8; nt++)
                    mma_tf32(acc[mt][nt], af[mt], bu0[nt], bu1[nt]);
        }
        if (pre) {
            const int nb = buf ^ 1;
#pragma unroll
            for (int p = 0; p < 2; p++) {
                const int row = arow0 + p * 64;
                As[nb][row][aw0 + 0] = rtf(pa[p].x);
                As[nb][row][aw0 + 2] = rtf(pa[p].y);
                As[nb][row][aw0 + 4] = rtf(pa[p].z);
                As[nb][row][aw0 + 6] = rtf(pa[p].w);
            }
#pragma unroll
            for (int p = 0; p < 2; p++) {
                const int rr = br + p * 8;
#pragma unroll
                for (int j = 0; j < 4; j++) {
                    const int n = bc + j;
                    const int sn = ((n >> 3) & 7) + ((n & 7) << 3) + (n & 64);
                    Bs[nb][rr][sn] = rtf(j == 0 ? pb[p].x : j == 1 ? pb[p].y : j == 2 ? pb[p].z : pb[p].w);
                }
            }
            __syncthreads();
            buf = nb;
        }
    }

    float p1[2][2], p2[2][2];
    if (EPI == 2) {
#pragma unroll
        for (int mt = 0; mt < 2; mt++)
#pragma unroll
            for (int hf = 0; hf < 2; hf++) { p1[mt][hf] = 0.f; p2[mt][hf] = 0.f; }
    }
#pragma unroll
    for (int mt = 0; mt < 2; mt++) {
#pragma unroll
        for (int half = 0; half < 2; half++) {
            const int row = wm + mt * 16 + g + half * 8;
            if (S == 1) {
                float* crow = C + (long long)(bm + row) * ldc;
#pragma unroll
                for (int nt = 0; nt < 8; nt++) {
                    const int col = wn + nt * 8 + 2 * q;
                    float v0 = acc[mt][nt][half * 2 + 0];
                    float v1 = acc[mt][nt][half * 2 + 1];
                    if (EPI == 1) {
                        v0 = v0 > 0.f ? v0 : (__expf(v0) - 1.f);
                        v1 = v1 > 0.f ? v1 : (__expf(v1) - 1.f);
                    }
                    if (EPI == 2) {
                        p1[mt][half] += v0 * ash[col] + v1 * ash[col + 1];
                        p2[mt][half] += v0 * ash[FF + col] + v1 * ash[FF + col + 1];
                    }
                    *(float2*)(crow + col) = make_float2(v0, v1);
                }
            } else {
                float* prow = Cpart + (long long)s * TOT + ((long long)z2 * M + bm + row) * 128;
#pragma unroll
                for (int nt = 0; nt < 8; nt++) {
                    const int col = wn + nt * 8 + 2 * q;
                    *(float2*)(prow + col) = make_float2(acc[mt][nt][half * 2 + 0],
                                                         acc[mt][nt][half * 2 + 1]);
                }
            }
        }
    }

    if (EPI == 2) {
#pragma unroll
        for (int mt = 0; mt < 2; mt++)
#pragma unroll
            for (int hf = 0; hf < 2; hf++) {
                p1[mt][hf] += __shfl_xor_sync(0xffffffffu, p1[mt][hf], 1);
                p1[mt][hf] += __shfl_xor_sync(0xffffffffu, p1[mt][hf], 2);
                p2[mt][hf] += __shfl_xor_sync(0xffffffffu, p2[mt][hf], 1);
                p2[mt][hf] += __shfl_xor_sync(0xffffffffu, p2[mt][hf], 2);
            }
        __syncthreads();
        if ((wid >> 2) == 0 && q == 0) {
#pragma unroll
            for (int mt = 0; mt < 2; mt++)
#pragma unroll
                for (int hf = 0; hf < 2; hf++) {
                    const int r = wm + mt * 16 + hf * 8 + g;
                    sv1[r] = p1[mt][hf];
                    sv2[r] = p2[mt][hf];
                }
        }
        __syncthreads();
        if ((wid >> 2) == 1 && q == 0) {
#pragma unroll
            for (int mt = 0; mt < 2; mt++)
#pragma unroll
                for (int hf = 0; hf < 2; hf++) {
                    const int r = wm + mt * 16 + hf * 8 + g;
                    const long long oidx = (long long)z2 * NN + bm + r;
                    o1[oidx] = sv1[r] + p1[mt][hf];
                    o2[oidx] = sv2[r] + p2[mt][hf];
                }
        }
    }
}

// ================= bf16 fused attention GEMM (round-14, validated) =================
#define SWX(row, w) ((w) ^ ((((row) >> 2) & 3) << 1))
template <int KC, int S, int EPI>
__global__ __launch_bounds__(256, 2)
void k_gatt16(const float* __restrict__ B,
              float* __restrict__ C, float* __restrict__ Cpart,
              int M,
              long long sBb, long long sBh,
              long long sCb, long long sCh,
              int Hb, int ldc, long long TOT,
              const unsigned* __restrict__ adjp,
              const float* __restrict__ a1p, const float* __restrict__ b1p,
              const float* __restrict__ s2lp) {
    const int zz = blockIdx.z;
    const int s = zz % S;
    const int z2 = zz / S;
    const int bz = z2 / Hb, hz = z2 % Hb;
    B += bz * sBb + hz * sBh + (long long)s * KC * 128;
    C += bz * sCb + hz * sCh;
    const int bm = blockIdx.y * 128;
    const int soff = s * KC;

    __shared__ unsigned As[2][128][8];
    __shared__ unsigned Bs[2][128][8];

    const int tid  = threadIdx.x;
    const int lane = tid & 31;
    const int wid  = tid >> 5;
    const int wm = (wid & 3) * 32;
    const int wn = (wid >> 2) * 64;
    const int q = lane & 3;
    const int g = lane >> 2;

    const int aj = tid & 3;
    const int arow0 = tid >> 2;
    const int bn = tid & 127;
    const int bh = tid >> 7;

    const unsigned* adjP = adjp + (long long)bz * NN * 16;
    const float* s2A = s2lp + (long long)z2 * NN;
    float A1r[2], B1r[2];
#pragma unroll
    for (int p = 0; p < 2; p++) {
        const long long ridx = (long long)z2 * NN + bm + arow0 + p * 64;
        A1r[p] = a1p[ridx];
        B1r[p] = b1p[ridx];
    }

    float acc[2][8][4];
#pragma unroll
    for (int i = 0; i < 2; i++)
#pragma unroll
        for (int j = 0; j < 8; j++)
#pragma unroll
            for (int r = 0; r < 4; r++) acc[i][j][r] = 0.f;

#define STAGE_A(bb, kk0, w0a, w1a, f2a, f2b)                                      \
    {                                                                              \
        const int bo = ((kk0) & 31) + 2 * aj;                                      \
        _Pragma("unroll")                                                          \
        for (int p = 0; p < 2; p++) {                                              \
            const int row = arow0 + p * 64;                                        \
            const unsigned w = (p == 0) ? (w0a) : (w1a);                           \
            const float f0 = att_f((w >> (bo + 0)) & 1u, (f2a).x, A1r[p], B1r[p]); \
            const float f1 = att_f((w >> (bo + 1)) & 1u, (f2a).y, A1r[p], B1r[p]); \
            const float f2 = att_f((w >> (bo + 8)) & 1u, (f2b).x, A1r[p], B1r[p]); \
            const float f3 = att_f((w >> (bo + 9)) & 1u, (f2b).y, A1r[p], B1r[p]); \
            *(uint2*)&As[bb][row][SWX(row, 2 * aj)] =                              \
                make_uint2(bf2(f0, f1), bf2(f2, f3));                              \
        }                                                                          \
    }
#define STAGE_B(bb, fv)                                                            \
    {                                                                              \
        *(uint2*)&Bs[bb][bn][SWX(bn, 2 * bh)] =                                    \
            make_uint2(bf2((fv)[0], (fv)[1]), bf2((fv)[2], (fv)[3]));              \
        *(uint2*)&Bs[bb][bn][SWX(bn, 2 * bh + 4)] =                                \
            make_uint2(bf2((fv)[4], (fv)[5]), bf2((fv)[6], (fv)[7]));              \
    }

    const int brow[8] = {2 * bh, 2 * bh + 1, 2 * bh + 8, 2 * bh + 9,
                         2 * bh + 4, 2 * bh + 5, 2 * bh + 12, 2 * bh + 13};

    {
        const int kk0 = soff;
        const int wix = kk0 >> 5;
        const unsigned w0 = adjP[(long long)(bm + arow0) * 16 + wix];
        const unsigned w1 = adjP[(long long)(bm + arow0 + 64) * 16 + wix];
        const float2 f2a = *(const float2*)(s2A + kk0 + 2 * aj);
        const float2 f2b = *(const float2*)(s2A + kk0 + 2 * aj + 8);
        STAGE_A(0, kk0, w0, w1, f2a, f2b);
        float fv[8];
#pragma unroll
        for (int i = 0; i < 8; i++) fv[i] = B[(long long)brow[i] * 128 + bn];
        STAGE_B(0, fv);
    }
    __syncthreads();

    int buf = 0;
#pragma unroll 2
    for (int k0 = 0; k0 < KC; k0 += 16) {
        const bool pre = (k0 + 16) < KC;
        unsigned pw0, pw1;
        float2 pf2a, pf2b;
        float pfv[8];
        if (pre) {
            const int kk0 = soff + k0 + 16;
            const int wix = kk0 >> 5;
            pw0 = adjP[(long long)(bm + arow0) * 16 + wix];
            pw1 = adjP[(long long)(bm + arow0 + 64) * 16 + wix];
            pf2a = *(const float2*)(s2A + kk0 + 2 * aj);
            pf2b = *(const float2*)(s2A + kk0 + 2 * aj + 8);
#pragma unroll
            for (int i = 0; i < 8; i++)
                pfv[i] = B[(long long)(k0 + 16 + brow[i]) * 128 + bn];
        }

        {
            unsigned bu[8][2];
#pragma unroll
            for (int nt = 0; nt < 8; nt++) {
                const int n0 = wn + nt * 8 + g;
                const uint2 t = *(const uint2*)&Bs[buf][n0][SWX(n0, 2 * q)];
                bu[nt][0] = t.x;
                bu[nt][1] = t.y;
            }
            unsigned af[2][4];
#pragma unroll
            for (int mt = 0; mt < 2; mt++) {
                const int m0 = wm + mt * 16 + g;
                const uint2 a = *(const uint2*)&As[buf][m0][SWX(m0, 2 * q)];
                const uint2 b = *(const uint2*)&As[buf][m0 + 8][SWX(m0 + 8, 2 * q)];
                af[mt][0] = a.x; af[mt][1] = b.x; af[mt][2] = a.y; af[mt][3] = b.y;
            }
#pragma unroll
            for (int mt = 0; mt < 2; mt++)
#pragma unroll
                for (int nt = 0; nt < 8; nt++)
                    mma_bf16(acc[mt][nt], af[mt], bu[nt][0], bu[nt][1]);
        }

        if (pre) {
            const int nb = buf ^ 1;
            STAGE_A(nb, soff + k0 + 16, pw0, pw1, pf2a, pf2b);
            STAGE_B(nb, pfv);
            __syncthreads();
            buf = nb;
        }
    }
#undef STAGE_A
#undef STAGE_B

#pragma unroll
    for (int mt = 0; mt < 2; mt++) {
#pragma unroll
        for (int half = 0; half < 2; half++) {
            const int row = wm + mt * 16 + g + half * 8;
            if (S == 1) {
                float* crow = C + (long long)(bm + row) * ldc;
#pragma unroll
                for (int nt = 0; nt < 8; nt++) {
                    const int col = wn + nt * 8 + 2 * q;
                    float v0 = acc[mt][nt][half * 2 + 0];
                    float v1 = acc[mt][nt][half * 2 + 1];
                    if (EPI == 1) {
                        v0 = v0 > 0.f ? v0 : (__expf(v0) - 1.f);
                        v1 = v1 > 0.f ? v1 : (__expf(v1) - 1.f);
                    }
                    *(float2*)(crow + col) = make_float2(v0, v1);
                }
            } else {
                float* prow = Cpart + (long long)s * TOT + ((long long)z2 * M + bm + row) * 128;
#pragma unroll
                for (int nt = 0; nt < 8; nt++) {
                    const int col = wn + nt * 8 + 2 * q;
                    *(float2*)(prow + col) = make_float2(acc[mt][nt][half * 2 + 0],
                                                         acc[mt][nt][half * 2 + 1]);
                }
            }
        }
    }
}

// ---------------- warp-per-row stats (packed adj, log2-domain factors) ----------------
__global__ void k_stats(const unsigned* __restrict__ adjp, const float* __restrict__ s1,
                        const float* __restrict__ s2, float* __restrict__ a1,
                        float* __restrict__ b1, float* __restrict__ s2l, int Hb) {
    const int lane = threadIdx.x & 31, wrp = threadIdx.x >> 5;
    const int n = blockIdx.x * 4 + wrp;
    const int h = blockIdx.y, b = blockIdx.z;
    const long idx = ((long)b * Hb + h) * NN + n;
    const float* s2row = s2 + ((long)b * Hb + h) * NN;
    const float s1v = s1[idx];
    const unsigned* arow = adjp + ((long)b * NN + n) * 16;

    float v[16];
    float mv = -INFINITY;
#pragma unroll
    for (int j = 0; j < 4; j++) {
        const int c0 = j * 128 + lane * 4;
        const unsigned w = arow[j * 4 + (lane >> 3)];
        const int bo = (lane * 4) & 31;
        const float4 sv = *(const float4*)(s2row + c0);
        float e0 = s1v + sv.x; e0 = e0 > 0.f ? e0 : 0.2f * e0;
        float e1 = s1v + sv.y; e1 = e1 > 0.f ? e1 : 0.2f * e1;
        float e2 = s1v + sv.z; e2 = e2 > 0.f ? e2 : 0.2f * e2;
        float e3 = s1v + sv.w; e3 = e3 > 0.f ? e3 : 0.2f * e3;
        v[j * 4 + 0] = ((w >> (bo + 0)) & 1u) ? e0 : NEGV;
        v[j * 4 + 1] = ((w >> (bo + 1)) & 1u) ? e1 : NEGV;
        v[j * 4 + 2] = ((w >> (bo + 2)) & 1u) ? e2 : NEGV;
        v[j * 4 + 3] = ((w >> (bo + 3)) & 1u) ? e3 : NEGV;
        mv = fmaxf(fmaxf(fmaxf(v[j * 4], v[j * 4 + 1]), fmaxf(v[j * 4 + 2], v[j * 4 + 3])), mv);
    }
    mv = warpMax(mv);
    float sum = 0.f;
#pragma unroll
    for (int j = 0; j < 16; j++) sum += __expf(v[j] - mv);
    sum = warpSum(sum);
    if (lane == 0) {
        const float li = -__log2f(sum);
        a1[idx] = (s1v - mv) * LOG2E + li;
        b1[idx] = (0.2f * s1v - mv) * LOG2E + li;
        s2l[idx] = s2[idx] * LOG2E;
    }
}

// ---------------- fused split-K(8) reduce + svec ----------------
__global__ void k_red_svec(const float* __restrict__ part, float* __restrict__ h2,
                           const float* __restrict__ a, float* __restrict__ t1,
                           float* __restrict__ t2, long long TOT) {
    const int row = blockIdx.x;
    const int t = threadIdx.x;
    const long long i = (long long)row * FF + t;
    float v = 0.f;
#pragma unroll
    for (int j = 0; j < 8; j++) v += part[(long long)j * TOT + i];
    h2[i] = v;
    float p1 = v * a[t];
    float p2 = v * a[FF + t];
    p1 = blockSum128(p1);
    p2 = blockSum128(p2);
    if (t == 0) {
        t1[row] = p1;
        t2[row] = p2;
    }
}

// ---------------- fused split-K(8) reduce + residual + layernorm (+relu) ----------------
__global__ void k_red_lnorm(const float* __restrict__ part, const float* __restrict__ res,
                            const float* __restrict__ g, const float* __restrict__ bb,
                            float* __restrict__ dst, int do_relu, long long TOT) {
    const int row = blockIdx.x;
    const int t = threadIdx.x;
    const long long i = (long long)row * FF + t;
    float o = 0.f;
#pragma unroll
    for (int j = 0; j < 8; j++) o += part[(long long)j * TOT + i];
    const float y = o + res[i];
    const float mu = blockSum128(y) * (1.f / FF);
    const float d = y - mu;
    const float var = blockSum128(d * d) * (1.f / FF);
    float r = d * rsqrtf(var + 1e-5f) * g[t] + bb[t];
    if (do_relu) r = fmaxf(r, 0.f);
    dst[i] = r;
}

// ---------------- host orchestration ----------------
extern "C" void kernel_launch(void* const* d_in, const int* in_sizes, int n_in,
                              void* d_out, int out_size) {
    (void)in_sizes; (void)n_in; (void)out_size;
    const float* x       = (const float*)d_in[0];
    const int*   adj     = (const int*)  d_in[1];
    const float* Wp      = (const float*)d_in[2];
    const float* bp      = (const float*)d_in[3];
    const float* W_heads = (const float*)d_in[4];
    const float* a_heads = (const float*)d_in[5];
    const float* W_out   = (const float*)d_in[6];
    const float* a_out   = (const float*)d_in[7];
    const float* ln_g    = (const float*)d_in[8];
    const float* ln_b    = (const float*)d_in[9];
    float* out = (float*)d_out;

    float *p_h, *p_hh, *p_multi, *p_h2, *p_part;
    float *p_s1, *p_s2, *p_a1, *p_b1, *p_s2l, *p_t1, *p_t2;
    unsigned* p_adjp;
    cudaGetSymbolAddress((void**)&p_h, g_h);
    cudaGetSymbolAddress((void**)&p_hh, g_hh);
    cudaGetSymbolAddress((void**)&p_multi, g_multi);
    cudaGetSymbolAddress((void**)&p_h2, g_h2);
    cudaGetSymbolAddress((void**)&p_part, g_part);
    cudaGetSymbolAddress((void**)&p_adjp, g_adjp);
    cudaGetSymbolAddress((void**)&p_s1, g_s1);
    cudaGetSymbolAddress((void**)&p_s2, g_s2);
    cudaGetSymbolAddress((void**)&p_a1, g_a1);
    cudaGetSymbolAddress((void**)&p_b1, g_b1);
    cudaGetSymbolAddress((void**)&p_s2l, g_s2l);
    cudaGetSymbolAddress((void**)&p_t1, g_t1);
    cudaGetSymbolAddress((void**)&p_t2, g_t2);

    const long long TOT = (long long)BATCH * NN * FF;   // 524288

    k_pack<<<BATCH * NN, 128>>>(adj, p_adjp);
    k_proj<<<BATCH * NN, 128>>>(x, Wp, bp, p_h);

    for (int l = 0; l < LL; l++) {
        // 1) per-head projection + fused svec (tf32 — logit path)
        k_gemm_t<128, 1, 2><<<dim3(1, NN / GBM, BATCH * HH), 256>>>(
            p_h, W_heads + (long)l * HH * FF * FF, p_hh, p_part,
            NN,
            (long long)NN * FF, 0,
            0, (long long)FF * FF,
            (long long)HH * NN * FF, (long long)NN * FF,
            HH, FF, 0,
            a_heads + (long)l * HH * 2 * FF, p_s1, p_s2);

        // 2) softmax factors (warp-per-row, packed adj)
        k_stats<<<dim3(NN / 4, HH, BATCH), 128>>>(p_adjp, p_s1, p_s2, p_a1, p_b1, p_s2l, HH);

        // 3) fused (softmax ∘ att) @ hh (bf16), ELU, scatter into multi
        k_gatt16<512, 1, 1><<<dim3(1, NN / 128, BATCH * HH), 256>>>(
            p_hh, p_multi, p_part,
            NN,
            (long long)HH * NN * FF, (long long)NN * FF,
            (long long)NN * HH * FF, (long long)FF,
            HH, HH * FF, 0,
            p_adjp, p_a1, p_b1, p_s2l);

        // 4) out projection (tf32 — logit path) split-K S=8 + fused reduce+svec
        k_gemm_t<128, 8, 0><<<dim3(1, (BATCH * NN) / GBM, 8), 256>>>(
            p_multi, W_out + (long)l * HH * FF * FF, p_h2, p_part,
            BATCH * NN,
            0, 0, 0, 0, 0, 0,
            1, FF, TOT,
            nullptr, nullptr, nullptr);
        k_red_svec<<<BATCH * NN, 128>>>(p_part, p_h2, a_out + (long)l * 2 * FF,
                                        p_t1, p_t2, TOT);

        // 5) single-head softmax factors
        k_stats<<<dim3(NN / 4, 1, BATCH), 128>>>(p_adjp, p_t1, p_t2, p_a1, p_b1, p_s2l, 1);

        // 6) fused (softmax ∘ att2) @ h2 (bf16), split-K S=8 + fused reduce+ln
        k_gatt16<64, 8, 0><<<dim3(1, NN / 128, BATCH * 8), 256>>>(
            p_h2, nullptr, p_part,
            NN,
            (long long)NN * FF, 0,
            0, 0,
            1, FF, TOT,
            p_adjp, p_a1, p_b1, p_s2l);
        float* dst = (l == LL - 1) ? out : p_h;
        k_red_lnorm<<<BATCH * NN, 128>>>(p_part, p_h,
                                         ln_g + (long)l * FF, ln_b + (long)l * FF,
                                         dst, (l < LL - 1) ? 1 : 0, TOT);
    }
}

// round 17
// speedup vs baseline: 1.4530x; 1.0538x over previous
#include <cuda_runtime.h>
#include <cuda_bf16.h>
#include <math.h>

// ---------------- problem constants ----------------
#define BATCH 8
#define NN    512
#define DIN   64
#define HH    8
#define FF    128
#define LL    2
#define NEGV  (-9e15f)
#define LOG2E 1.4426950408889634f

// ---------------- scratch (device globals; no allocs) ----------------
__device__ float    g_h    [BATCH * NN * FF];
__device__ float    g_hh   [BATCH * HH * NN * FF];
__device__ float    g_multi[BATCH * NN * HH * FF];
__device__ float    g_h2   [BATCH * NN * FF];
__device__ float    g_part [8 * BATCH * NN * FF];
__device__ unsigned g_adjp [BATCH * NN * 16];
__device__ float    g_s1   [BATCH * HH * NN];
__device__ float    g_s2   [BATCH * HH * NN];
__device__ float    g_ea1  [BATCH * HH * NN];   // ex2((s1-mx)*log2e - log2(sum))   (row factor, pos branch)
__device__ float    g_eb1  [BATCH * HH * NN];   // ex2((0.2 s1-mx)*log2e - log2(sum)) (row factor, neg branch)
__device__ float    g_e2a  [BATCH * HH * NN];   // ex2(s2*log2e)       (col factor, pos branch)
__device__ float    g_e2b  [BATCH * HH * NN];   // ex2(0.2 s2*log2e)   (col factor, neg branch)
__device__ float    g_t1   [BATCH * NN];
__device__ float    g_t2   [BATCH * NN];

// ---------------- reductions ----------------
__device__ __forceinline__ float warpSum(float v) {
#pragma unroll
    for (int o = 16; o > 0; o >>= 1) v += __shfl_xor_sync(0xffffffffu, v, o);
    return v;
}
__device__ __forceinline__ float warpMax(float v) {
#pragma unroll
    for (int o = 16; o > 0; o >>= 1) v = fmaxf(v, __shfl_xor_sync(0xffffffffu, v, o));
    return v;
}
__device__ __forceinline__ float blockSum128(float v) {
    __shared__ float sh[4];
    v = warpSum(v);
    __syncthreads();
    if ((threadIdx.x & 31) == 0) sh[threadIdx.x >> 5] = v;
    __syncthreads();
    return sh[0] + sh[1] + sh[2] + sh[3];
}

// ---------------- numeric helpers ----------------
__device__ __forceinline__ unsigned rtf(float f) {
    return __float_as_uint(f) + 0x1000u;   // RNA-to-tf32 via int add
}
__device__ __forceinline__ void mma_tf32(float c[4], const unsigned a[4], const unsigned b0, const unsigned b1) {
    asm("mma.sync.aligned.m16n8k8.row.col.f32.tf32.tf32.f32 "
        "{%0,%1,%2,%3},{%4,%5,%6,%7},{%8,%9},{%0,%1,%2,%3};"
        : "+f"(c[0]), "+f"(c[1]), "+f"(c[2]), "+f"(c[3])
        : "r"(a[0]), "r"(a[1]), "r"(a[2]), "r"(a[3]), "r"(b0), "r"(b1));
}
__device__ __forceinline__ void mma_bf16(float c[4], const unsigned a[4], const unsigned b0, const unsigned b1) {
    asm("mma.sync.aligned.m16n8k16.row.col.f32.bf16.bf16.f32 "
        "{%0,%1,%2,%3},{%4,%5,%6,%7},{%8,%9},{%0,%1,%2,%3};"
        : "+f"(c[0]), "+f"(c[1]), "+f"(c[2]), "+f"(c[3])
        : "r"(a[0]), "r"(a[1]), "r"(a[2]), "r"(a[3]), "r"(b0), "r"(b1));
}
__device__ __forceinline__ unsigned bf2(float lo, float hi) {
    unsigned r;
    asm("cvt.rn.bf16x2.f32 %0, %1, %2;" : "=r"(r) : "f"(hi), "f"(lo));
    return r;
}
__device__ __forceinline__ float ex2f(float x) {
    float r;
    asm("ex2.approx.f32 %0, %1;" : "=f"(r) : "f"(x));
    return r;
}
// att element, exp factored out: bit ? max(eA1*e2a, eB1*e2b) : 0
__device__ __forceinline__ float att_m(unsigned bit, float e2a, float e2b, float eA1, float eB1) {
    const float r = fmaxf(eA1 * e2a, eB1 * e2b);
    return bit ? r : 0.f;
}

// ---------------- adjacency bit-pack (one-time) ----------------
__global__ void k_pack(const int* __restrict__ adj, unsigned* __restrict__ packed) {
    const long long row = blockIdx.x;
    const int t = threadIdx.x;
    const int w = t >> 5, lane = t & 31;
#pragma unroll
    for (int p = 0; p < 4; p++) {
        const int col = p * 128 + w * 32 + lane;
        const unsigned m = __ballot_sync(0xffffffffu, adj[row * NN + col] > 0);
        if (lane == 0) packed[row * 16 + p * 4 + w] = m;
    }
}

// ---------------- input projection ----------------
__global__ void k_proj(const float* __restrict__ x, const float* __restrict__ Wp,
                       const float* __restrict__ bp, float* __restrict__ h) {
    __shared__ float xs[DIN];
    const int row = blockIdx.x;
    const int t = threadIdx.x;
    if (t < DIN) xs[t] = x[(long)row * DIN + t];
    __syncthreads();
    float acc = bp[t];
#pragma unroll
    for (int i = 0; i < DIN; i++) acc = fmaf(xs[i], Wp[i * FF + t], acc);
    h[(long)row * FF + t] = fmaxf(acc, 0.f);
}

// ================= tf32 GEMM (projections — logit path stays tf32) =================
#define GBM 128
#define GBK 16
#define ALD 24
#define BLD 136
template <int KC, int S, int EPI>
__global__ __launch_bounds__(256, 2)
void k_gemm_t(const float* __restrict__ A, const float* __restrict__ B,
              float* __restrict__ C, float* __restrict__ Cpart,
              int M,
              long long sAb, long long sAh,
              long long sBb, long long sBh,
              long long sCb, long long sCh,
              int Hb, int ldc, long long TOT,
              const float* __restrict__ avec,
              float* __restrict__ o1, float* __restrict__ o2) {
    const int zz = blockIdx.z;
    const int s = zz % S;
    const int z2 = zz / S;
    const int bz = z2 / Hb, hz = z2 % Hb;
    A += bz * sAb + hz * sAh + (long long)s * KC;
    B += bz * sBb + hz * sBh + (long long)s * KC * 128;
    C += bz * sCb + hz * sCh;
    const int bm = blockIdx.y * GBM;
    constexpr long long Kfull = (long long)KC * S;

    __shared__ unsigned As[2][GBM][ALD];
    __shared__ unsigned Bs[2][GBK][BLD];
    __shared__ float ash[2 * FF];
    __shared__ float sv1[GBM], sv2[GBM];

    const int tid  = threadIdx.x;
    const int lane = tid & 31;
    const int wid  = tid >> 5;
    const int wm = (wid & 3) * 32;
    const int wn = (wid >> 2) * 64;
    const int q = lane & 3;
    const int g = lane >> 2;

    const int arow0 = tid >> 2;
    const int ac = tid & 3;
    const int aw0 = (ac & 1) + 8 * (ac >> 1);
    const int br = tid >> 5;
    const int bc = lane * 4;

    if (EPI == 2 && tid < 2 * FF) ash[tid] = (avec + (long long)hz * 2 * FF)[tid];

    float acc[2][8][4];
#pragma unroll
    for (int i = 0; i < 2; i++)
#pragma unroll
        for (int j = 0; j < 8; j++)
#pragma unroll
            for (int r = 0; r < 4; r++) acc[i][j][r] = 0.f;

#pragma unroll
    for (int p = 0; p < 2; p++) {
        const int row = arow0 + p * 64;
        const float4 av = *(const float4*)(A + (long long)(bm + row) * Kfull + ac * 4);
        As[0][row][aw0 + 0] = rtf(av.x);
        As[0][row][aw0 + 2] = rtf(av.y);
        As[0][row][aw0 + 4] = rtf(av.z);
        As[0][row][aw0 + 6] = rtf(av.w);
    }
#pragma unroll
    for (int p = 0; p < 2; p++) {
        const int rr = br + p * 8;
        const float4 bv = *(const float4*)(B + (long long)rr * 128 + bc);
#pragma unroll
        for (int j = 0; j < 4; j++) {
            const int n = bc + j;
            const int sn = ((n >> 3) & 7) + ((n & 7) << 3) + (n & 64);
            Bs[0][rr][sn] = rtf(j == 0 ? bv.x : j == 1 ? bv.y : j == 2 ? bv.z : bv.w);
        }
    }
    __syncthreads();

    int buf = 0;
#pragma unroll 2
    for (int k0 = 0; k0 < KC; k0 += GBK) {
        const bool pre = (k0 + GBK) < KC;
        float4 pa[2], pb[2];
        if (pre) {
            const int kn = k0 + GBK;
#pragma unroll
            for (int p = 0; p < 2; p++) {
                const int row = arow0 + p * 64;
                pa[p] = *(const float4*)(A + (long long)(bm + row) * Kfull + kn + ac * 4);
            }
#pragma unroll
            for (int p = 0; p < 2; p++) {
                const int rr = br + p * 8;
                pb[p] = *(const float4*)(B + (long long)(kn + rr) * 128 + bc);
            }
        }
#pragma unroll
        for (int ks = 0; ks < GBK; ks += 8) {
            const unsigned* r0 = &Bs[buf][ks + q][0];
            const unsigned* r1 = &Bs[buf][ks + q + 4][0];
            const uint4 b0a = *(const uint4*)(r0 + wn + 8 * g);
            const uint4 b0b = *(const uint4*)(r0 + wn + 8 * g + 4);
            const uint4 b1a = *(const uint4*)(r1 + wn + 8 * g);
            const uint4 b1b = *(const uint4*)(r1 + wn + 8 * g + 4);
            const unsigned bu0[8] = {b0a.x, b0a.y, b0a.z, b0a.w, b0b.x, b0b.y, b0b.z, b0b.w};
            const unsigned bu1[8] = {b1a.x, b1a.y, b1a.z, b1a.w, b1b.x, b1b.y, b1b.z, b1b.w};
            unsigned af[2][4];
#pragma unroll
            for (int mt = 0; mt < 2; mt++) {
                const int m0 = wm + mt * 16 + g;
                const uint2 a0 = *(const uint2*)&As[buf][m0][ks + 2 * q];
                const uint2 a1 = *(const uint2*)&As[buf][m0 + 8][ks + 2 * q];
                af[mt][0] = a0.x; af[mt][1] = a1.x; af[mt][2] = a0.y; af[mt][3] = a1.y;
            }
#pragma unroll
            for (int mt = 0; mt < 2; mt++)
#pragma unroll
                for (int nt = 0; nt < 8; nt++)
                    mma_tf32(acc[mt][nt], af[mt], bu0[nt], bu1[nt]);
        }
        if (pre) {
            const int nb = buf ^ 1;
#pragma unroll
            for (int p = 0; p < 2; p++) {
                const int row = arow0 + p * 64;
                As[nb][row][aw0 + 0] = rtf(pa[p].x);
                As[nb][row][aw0 + 2] = rtf(pa[p].y);
                As[nb][row][aw0 + 4] = rtf(pa[p].z);
                As[nb][row][aw0 + 6] = rtf(pa[p].w);
            }
#pragma unroll
            for (int p = 0; p < 2; p++) {
                const int rr = br + p * 8;
#pragma unroll
                for (int j = 0; j < 4; j++) {
                    const int n = bc + j;
                    const int sn = ((n >> 3) & 7) + ((n & 7) << 3) + (n & 64);
                    Bs[nb][rr][sn] = rtf(j == 0 ? pb[p].x : j == 1 ? pb[p].y : j == 2 ? pb[p].z : pb[p].w);
                }
            }
            __syncthreads();
            buf = nb;
        }
    }

    float p1[2][2], p2[2][2];
    if (EPI == 2) {
#pragma unroll
        for (int mt = 0; mt < 2; mt++)
#pragma unroll
            for (int hf = 0; hf < 2; hf++) { p1[mt][hf] = 0.f; p2[mt][hf] = 0.f; }
    }
#pragma unroll
    for (int mt = 0; mt < 2; mt++) {
#pragma unroll
        for (int half = 0; half < 2; half++) {
            const int row = wm + mt * 16 + g + half * 8;
            if (S == 1) {
                float* crow = C + (long long)(bm + row) * ldc;
#pragma unroll
                for (int nt = 0; nt < 8; nt++) {
                    const int col = wn + nt * 8 + 2 * q;
                    float v0 = acc[mt][nt][half * 2 + 0];
                    float v1 = acc[mt][nt][half * 2 + 1];
                    if (EPI == 1) {
                        v0 = v0 > 0.f ? v0 : (__expf(v0) - 1.f);
                        v1 = v1 > 0.f ? v1 : (__expf(v1) - 1.f);
                    }
                    if (EPI == 2) {
                        p1[mt][half] += v0 * ash[col] + v1 * ash[col + 1];
                        p2[mt][half] += v0 * ash[FF + col] + v1 * ash[FF + col + 1];
                    }
                    *(float2*)(crow + col) = make_float2(v0, v1);
                }
            } else {
                float* prow = Cpart + (long long)s * TOT + ((long long)z2 * M + bm + row) * 128;
#pragma unroll
                for (int nt = 0; nt < 8; nt++) {
                    const int col = wn + nt * 8 + 2 * q;
                    *(float2*)(prow + col) = make_float2(acc[mt][nt][half * 2 + 0],
                                                         acc[mt][nt][half * 2 + 1]);
                }
            }
        }
    }

    if (EPI == 2) {
#pragma unroll
        for (int mt = 0; mt < 2; mt++)
#pragma unroll
            for (int hf = 0; hf < 2; hf++) {
                p1[mt][hf] += __shfl_xor_sync(0xffffffffu, p1[mt][hf], 1);
                p1[mt][hf] += __shfl_xor_sync(0xffffffffu, p1[mt][hf], 2);
                p2[mt][hf] += __shfl_xor_sync(0xffffffffu, p2[mt][hf], 1);
                p2[mt][hf] += __shfl_xor_sync(0xffffffffu, p2[mt][hf], 2);
            }
        __syncthreads();
        if ((wid >> 2) == 0 && q == 0) {
#pragma unroll
            for (int mt = 0; mt < 2; mt++)
#pragma unroll
                for (int hf = 0; hf < 2; hf++) {
                    const int r = wm + mt * 16 + hf * 8 + g;
                    sv1[r] = p1[mt][hf];
                    sv2[r] = p2[mt][hf];
                }
        }
        __syncthreads();
        if ((wid >> 2) == 1 && q == 0) {
#pragma unroll
            for (int mt = 0; mt < 2; mt++)
#pragma unroll
                for (int hf = 0; hf < 2; hf++) {
                    const int r = wm + mt * 16 + hf * 8 + g;
                    const long long oidx = (long long)z2 * NN + bm + r;
                    o1[oidx] = sv1[r] + p1[mt][hf];
                    o2[oidx] = sv2[r] + p2[mt][hf];
                }
        }
    }
}

// ================= bf16 fused attention GEMM (exp factored out of hot loop) =================
#define SWX(row, w) ((w) ^ ((((row) >> 2) & 3) << 1))
template <int KC, int S, int EPI>
__global__ __launch_bounds__(256, 2)
void k_gatt16(const float* __restrict__ B,
              float* __restrict__ C, float* __restrict__ Cpart,
              int M,
              long long sBb, long long sBh,
              long long sCb, long long sCh,
              int Hb, int ldc, long long TOT,
              const unsigned* __restrict__ adjp,
              const float* __restrict__ ea1p, const float* __restrict__ eb1p,
              const float* __restrict__ e2ap, const float* __restrict__ e2bp) {
    const int zz = blockIdx.z;
    const int s = zz % S;
    const int z2 = zz / S;
    const int bz = z2 / Hb, hz = z2 % Hb;
    B += bz * sBb + hz * sBh + (long long)s * KC * 128;
    C += bz * sCb + hz * sCh;
    const int bm = blockIdx.y * 128;
    const int soff = s * KC;

    __shared__ unsigned As[2][128][8];
    __shared__ unsigned Bs[2][128][8];

    const int tid  = threadIdx.x;
    const int lane = tid & 31;
    const int wid  = tid >> 5;
    const int wm = (wid & 3) * 32;
    const int wn = (wid >> 2) * 64;
    const int q = lane & 3;
    const int g = lane >> 2;

    const int aj = tid & 3;
    const int arow0 = tid >> 2;
    const int bn = tid & 127;
    const int bh = tid >> 7;

    const unsigned* adjP = adjp + (long long)bz * NN * 16;
    const float* eaA = e2ap + (long long)z2 * NN;
    const float* ebA = e2bp + (long long)z2 * NN;
    float A1r[2], B1r[2];
#pragma unroll
    for (int p = 0; p < 2; p++) {
        const long long ridx = (long long)z2 * NN + bm + arow0 + p * 64;
        A1r[p] = ea1p[ridx];
        B1r[p] = eb1p[ridx];
    }

    float acc[2][8][4];
#pragma unroll
    for (int i = 0; i < 2; i++)
#pragma unroll
        for (int j = 0; j < 8; j++)
#pragma unroll
            for (int r = 0; r < 4; r++) acc[i][j][r] = 0.f;

#define STAGE_A(bb, kk0, w0a, w1a, eal, eah, ebl, ebh)                             \
    {                                                                              \
        const int bo = ((kk0) & 31) + 2 * aj;                                      \
        _Pragma("unroll")                                                          \
        for (int p = 0; p < 2; p++) {                                              \
            const int row = arow0 + p * 64;                                        \
            const unsigned w = (p == 0) ? (w0a) : (w1a);                           \
            const float f0 = att_m((w >> (bo + 0)) & 1u, (eal).x, (ebl).x, A1r[p], B1r[p]); \
            const float f1 = att_m((w >> (bo + 1)) & 1u, (eal).y, (ebl).y, A1r[p], B1r[p]); \
            const float f2 = att_m((w >> (bo + 8)) & 1u, (eah).x, (ebh).x, A1r[p], B1r[p]); \
            const float f3 = att_m((w >> (bo + 9)) & 1u, (eah).y, (ebh).y, A1r[p], B1r[p]); \
            *(uint2*)&As[bb][row][SWX(row, 2 * aj)] =                              \
                make_uint2(bf2(f0, f1), bf2(f2, f3));                              \
        }                                                                          \
    }
#define STAGE_B(bb, fv)                                                            \
    {                                                                              \
        *(uint2*)&Bs[bb][bn][SWX(bn, 2 * bh)] =                                    \
            make_uint2(bf2((fv)[0], (fv)[1]), bf2((fv)[2], (fv)[3]));              \
        *(uint2*)&Bs[bb][bn][SWX(bn, 2 * bh + 4)] =                                \
            make_uint2(bf2((fv)[4], (fv)[5]), bf2((fv)[6], (fv)[7]));              \
    }

    const int brow[8] = {2 * bh, 2 * bh + 1, 2 * bh + 8, 2 * bh + 9,
                         2 * bh + 4, 2 * bh + 5, 2 * bh + 12, 2 * bh + 13};

    // ---- prologue: chunk 0 ----
    {
        const int kk0 = soff;
        const int wix = kk0 >> 5;
        const unsigned w0 = adjP[(long long)(bm + arow0) * 16 + wix];
        const unsigned w1 = adjP[(long long)(bm + arow0 + 64) * 16 + wix];
        const float2 eal = *(const float2*)(eaA + kk0 + 2 * aj);
        const float2 eah = *(const float2*)(eaA + kk0 + 2 * aj + 8);
        const float2 ebl = *(const float2*)(ebA + kk0 + 2 * aj);
        const float2 ebh = *(const float2*)(ebA + kk0 + 2 * aj + 8);
        STAGE_A(0, kk0, w0, w1, eal, eah, ebl, ebh);
        float fv[8];
#pragma unroll
        for (int i = 0; i < 8; i++) fv[i] = B[(long long)brow[i] * 128 + bn];
        STAGE_B(0, fv);
    }
    __syncthreads();

    int buf = 0;
#pragma unroll 2
    for (int k0 = 0; k0 < KC; k0 += 16) {
        const bool pre = (k0 + 16) < KC;
        unsigned pw0, pw1;
        float2 peal, peah, pebl, pebh;
        float pfv[8];
        if (pre) {
            const int kk0 = soff + k0 + 16;
            const int wix = kk0 >> 5;
            pw0 = adjP[(long long)(bm + arow0) * 16 + wix];
            pw1 = adjP[(long long)(bm + arow0 + 64) * 16 + wix];
            peal = *(const float2*)(eaA + kk0 + 2 * aj);
            peah = *(const float2*)(eaA + kk0 + 2 * aj + 8);
            pebl = *(const float2*)(ebA + kk0 + 2 * aj);
            pebh = *(const float2*)(ebA + kk0 + 2 * aj + 8);
#pragma unroll
            for (int i = 0; i < 8; i++)
                pfv[i] = B[(long long)(k0 + 16 + brow[i]) * 128 + bn];
        }

        // ---- compute: one m16n8k16 per (mt,nt) ----
        {
            unsigned bu[8][2];
#pragma unroll
            for (int nt = 0; nt < 8; nt++) {
                const int n0 = wn + nt * 8 + g;
                const uint2 t = *(const uint2*)&Bs[buf][n0][SWX(n0, 2 * q)];
                bu[nt][0] = t.x;
                bu[nt][1] = t.y;
            }
            unsigned af[2][4];
#pragma unroll
            for (int mt = 0; mt < 2; mt++) {
                const int m0 = wm + mt * 16 + g;
                const uint2 a = *(const uint2*)&As[buf][m0][SWX(m0, 2 * q)];
                const uint2 b = *(const uint2*)&As[buf][m0 + 8][SWX(m0 + 8, 2 * q)];
                af[mt][0] = a.x; af[mt][1] = b.x; af[mt][2] = a.y; af[mt][3] = b.y;
            }
#pragma unroll
            for (int mt = 0; mt < 2; mt++)
#pragma unroll
                for (int nt = 0; nt < 8; nt++)
                    mma_bf16(acc[mt][nt], af[mt], bu[nt][0], bu[nt][1]);
        }

        if (pre) {
            const int nb = buf ^ 1;
            STAGE_A(nb, soff + k0 + 16, pw0, pw1, peal, peah, pebl, pebh);
            STAGE_B(nb, pfv);
            __syncthreads();
            buf = nb;
        }
    }
#undef STAGE_A
#undef STAGE_B

    // ---- epilogue ----
#pragma unroll
    for (int mt = 0; mt < 2; mt++) {
#pragma unroll
        for (int half = 0; half < 2; half++) {
            const int row = wm + mt * 16 + g + half * 8;
            if (S == 1) {
                float* crow = C + (long long)(bm + row) * ldc;
#pragma unroll
                for (int nt = 0; nt < 8; nt++) {
                    const int col = wn + nt * 8 + 2 * q;
                    float v0 = acc[mt][nt][half * 2 + 0];
                    float v1 = acc[mt][nt][half * 2 + 1];
                    if (EPI == 1) {
                        v0 = v0 > 0.f ? v0 : (__expf(v0) - 1.f);
                        v1 = v1 > 0.f ? v1 : (__expf(v1) - 1.f);
                    }
                    *(float2*)(crow + col) = make_float2(v0, v1);
                }
            } else {
                float* prow = Cpart + (long long)s * TOT + ((long long)z2 * M + bm + row) * 128;
#pragma unroll
                for (int nt = 0; nt < 8; nt++) {
                    const int col = wn + nt * 8 + 2 * q;
                    *(float2*)(prow + col) = make_float2(acc[mt][nt][half * 2 + 0],
                                                         acc[mt][nt][half * 2 + 1]);
                }
            }
        }
    }
}

// ---------------- warp-per-row stats: exp-factored attention factors ----------------
__global__ void k_stats(const unsigned* __restrict__ adjp, const float* __restrict__ s1,
                        const float* __restrict__ s2, float* __restrict__ ea1,
                        float* __restrict__ eb1, float* __restrict__ e2a,
                        float* __restrict__ e2b, int Hb) {
    const int lane = threadIdx.x & 31, wrp = threadIdx.x >> 5;
    const int n = blockIdx.x * 4 + wrp;
    const int h = blockIdx.y, b = blockIdx.z;
    const long idx = ((long)b * Hb + h) * NN + n;
    const float* s2row = s2 + ((long)b * Hb + h) * NN;
    const float s1v = s1[idx];
    const unsigned* arow = adjp + ((long)b * NN + n) * 16;

    float v[16];
    float mv = -INFINITY;
#pragma unroll
    for (int j = 0; j < 4; j++) {
        const int c0 = j * 128 + lane * 4;
        const unsigned w = arow[j * 4 + (lane >> 3)];
        const int bo = (lane * 4) & 31;
        const float4 sv = *(const float4*)(s2row + c0);
        float e0 = s1v + sv.x; e0 = e0 > 0.f ? e0 : 0.2f * e0;
        float e1 = s1v + sv.y; e1 = e1 > 0.f ? e1 : 0.2f * e1;
        float e2 = s1v + sv.z; e2 = e2 > 0.f ? e2 : 0.2f * e2;
        float e3 = s1v + sv.w; e3 = e3 > 0.f ? e3 : 0.2f * e3;
        v[j * 4 + 0] = ((w >> (bo + 0)) & 1u) ? e0 : NEGV;
        v[j * 4 + 1] = ((w >> (bo + 1)) & 1u) ? e1 : NEGV;
        v[j * 4 + 2] = ((w >> (bo + 2)) & 1u) ? e2 : NEGV;
        v[j * 4 + 3] = ((w >> (bo + 3)) & 1u) ? e3 : NEGV;
        mv = fmaxf(fmaxf(fmaxf(v[j * 4], v[j * 4 + 1]), fmaxf(v[j * 4 + 2], v[j * 4 + 3])), mv);
    }
    mv = warpMax(mv);
    float sum = 0.f;
#pragma unroll
    for (int j = 0; j < 16; j++) sum += __expf(v[j] - mv);
    sum = warpSum(sum);
    if (lane == 0) {
        const float li = -__log2f(sum);
        ea1[idx] = ex2f((s1v - mv) * LOG2E + li);
        eb1[idx] = ex2f((0.2f * s1v - mv) * LOG2E + li);
        const float s2v = s2[idx];
        e2a[idx] = ex2f(s2v * LOG2E);
        e2b[idx] = ex2f(0.2f * s2v * LOG2E);
    }
}

// ---------------- fused split-K(8) reduce + svec ----------------
__global__ void k_red_svec(const float* __restrict__ part, float* __restrict__ h2,
                           const float* __restrict__ a, float* __restrict__ t1,
                           float* __restrict__ t2, long long TOT) {
    const int row = blockIdx.x;
    const int t = threadIdx.x;
    const long long i = (long long)row * FF + t;
    float v = 0.f;
#pragma unroll
    for (int j = 0; j < 8; j++) v += part[(long long)j * TOT + i];
    h2[i] = v;
    float p1 = v * a[t];
    float p2 = v * a[FF + t];
    p1 = blockSum128(p1);
    p2 = blockSum128(p2);
    if (t == 0) {
        t1[row] = p1;
        t2[row] = p2;
    }
}

// ---------------- fused split-K(8) reduce + residual + layernorm (+relu) ----------------
__global__ void k_red_lnorm(const float* __restrict__ part, const float* __restrict__ res,
                            const float* __restrict__ g, const float* __restrict__ bb,
                            float* __restrict__ dst, int do_relu, long long TOT) {
    const int row = blockIdx.x;
    const int t = threadIdx.x;
    const long long i = (long long)row * FF + t;
    float o = 0.f;
#pragma unroll
    for (int j = 0; j < 8; j++) o += part[(long long)j * TOT + i];
    const float y = o + res[i];
    const float mu = blockSum128(y) * (1.f / FF);
    const float d = y - mu;
    const float var = blockSum128(d * d) * (1.f / FF);
    float r = d * rsqrtf(var + 1e-5f) * g[t] + bb[t];
    if (do_relu) r = fmaxf(r, 0.f);
    dst[i] = r;
}

// ---------------- host orchestration ----------------
extern "C" void kernel_launch(void* const* d_in, const int* in_sizes, int n_in,
                              void* d_out, int out_size) {
    (void)in_sizes; (void)n_in; (void)out_size;
    const float* x       = (const float*)d_in[0];
    const int*   adj     = (const int*)  d_in[1];
    const float* Wp      = (const float*)d_in[2];
    const float* bp      = (const float*)d_in[3];
    const float* W_heads = (const float*)d_in[4];
    const float* a_heads = (const float*)d_in[5];
    const float* W_out   = (const float*)d_in[6];
    const float* a_out   = (const float*)d_in[7];
    const float* ln_g    = (const float*)d_in[8];
    const float* ln_b    = (const float*)d_in[9];
    float* out = (float*)d_out;

    float *p_h, *p_hh, *p_multi, *p_h2, *p_part;
    float *p_s1, *p_s2, *p_ea1, *p_eb1, *p_e2a, *p_e2b, *p_t1, *p_t2;
    unsigned* p_adjp;
    cudaGetSymbolAddress((void**)&p_h, g_h);
    cudaGetSymbolAddress((void**)&p_hh, g_hh);
    cudaGetSymbolAddress((void**)&p_multi, g_multi);
    cudaGetSymbolAddress((void**)&p_h2, g_h2);
    cudaGetSymbolAddress((void**)&p_part, g_part);
    cudaGetSymbolAddress((void**)&p_adjp, g_adjp);
    cudaGetSymbolAddress((void**)&p_s1, g_s1);
    cudaGetSymbolAddress((void**)&p_s2, g_s2);
    cudaGetSymbolAddress((void**)&p_ea1, g_ea1);
    cudaGetSymbolAddress((void**)&p_eb1, g_eb1);
    cudaGetSymbolAddress((void**)&p_e2a, g_e2a);
    cudaGetSymbolAddress((void**)&p_e2b, g_e2b);
    cudaGetSymbolAddress((void**)&p_t1, g_t1);
    cudaGetSymbolAddress((void**)&p_t2, g_t2);

    const long long TOT = (long long)BATCH * NN * FF;   // 524288

    k_pack<<<BATCH * NN, 128>>>(adj, p_adjp);
    k_proj<<<BATCH * NN, 128>>>(x, Wp, bp, p_h);

    for (int l = 0; l < LL; l++) {
        // 1) per-head projection + fused svec (tf32 — logit path)
        k_gemm_t<128, 1, 2><<<dim3(1, NN / GBM, BATCH * HH), 256>>>(
            p_h, W_heads + (long)l * HH * FF * FF, p_hh, p_part,
            NN,
            (long long)NN * FF, 0,
            0, (long long)FF * FF,
            (long long)HH * NN * FF, (long long)NN * FF,
            HH, FF, 0,
            a_heads + (long)l * HH * 2 * FF, p_s1, p_s2);

        // 2) softmax factors (warp-per-row, exp factored)
        k_stats<<<dim3(NN / 4, HH, BATCH), 128>>>(p_adjp, p_s1, p_s2,
                                                  p_ea1, p_eb1, p_e2a, p_e2b, HH);

        // 3) fused (softmax ∘ att) @ hh (bf16, no exp in hot loop), ELU, scatter into multi
        k_gatt16<512, 1, 1><<<dim3(1, NN / 128, BATCH * HH), 256>>>(
            p_hh, p_multi, p_part,
            NN,
            (long long)HH * NN * FF, (long long)NN * FF,
            (long long)NN * HH * FF, (long long)FF,
            HH, HH * FF, 0,
            p_adjp, p_ea1, p_eb1, p_e2a, p_e2b);

        // 4) out projection (tf32 — logit path) split-K S=8 + fused reduce+svec
        k_gemm_t<128, 8, 0><<<dim3(1, (BATCH * NN) / GBM, 8), 256>>>(
            p_multi, W_out + (long)l * HH * FF * FF, p_h2, p_part,
            BATCH * NN,
            0, 0, 0, 0, 0, 0,
            1, FF, TOT,
            nullptr, nullptr, nullptr);
        k_red_svec<<<BATCH * NN, 128>>>(p_part, p_h2, a_out + (long)l * 2 * FF,
                                        p_t1, p_t2, TOT);

        // 5) single-head softmax factors
        k_stats<<<dim3(NN / 4, 1, BATCH), 128>>>(p_adjp, p_t1, p_t2,
                                                 p_ea1, p_eb1, p_e2a, p_e2b, 1);

        // 6) fused (softmax ∘ att2) @ h2 (bf16), split-K S=8 + fused reduce+ln
        k_gatt16<64, 8, 0><<<dim3(1, NN / 128, BATCH * 8), 256>>>(
            p_h2, nullptr, p_part,
            NN,
            (long long)NN * FF, 0,
            0, 0,
            1, FF, TOT,
            p_adjp, p_ea1, p_eb1, p_e2a, p_e2b);
        float* dst = (l == LL - 1) ? out : p_h;
        k_red_lnorm<<<BATCH * NN, 128>>>(p_part, p_h,
                                         ln_g + (long)l * FF, ln_b + (long)l * FF,
                                         dst, (l < LL - 1) ? 1 : 0, TOT);
    }
}